// round 9
// baseline (speedup 1.0000x reference)
#include <cuda_runtime.h>
#include <cuda_fp16.h>
#include <cfloat>
#include <cstdint>

#define NV 16
#define NN 8192
#define ND 256
#define NK 1024
#define W1 0.26f          // coarse-score uncertainty window
#define MARGIN 0.05f      // fp32-exact pair-adjudication margin

// ---- smem layout (bytes) ----
// A resident: 4 d-tiles x (64 rows x 144B)  = 36864
// B ring:     3 bufs   x (128 rows x 144B)  = 55296
#define ROWB   144
#define ATILB  9216
#define BTILB  18432
#define AOFF   0
#define BOFF   36864
#define WSQ_S  92160
#define MRG    96256          // 4 n-groups x 64 rows x 3 x (4+4)B = 6144
#define SMEM_TOTAL 102400

// ---- device scratch ----
__device__ float  g_wsq[NV * NK];
__device__ float  g_Wt[(size_t)NV * NK * ND];                    // [V][K][D] fp32
__device__ __align__(256) __half g_Xh[(size_t)NV * NN * ND];     // X fp16
__device__ __align__(256) __half g_Wh[(size_t)NV * NK * ND];     // Wt fp16
__device__ int    g_idx[NV * NN];
__device__ int    g_fix_count;
__device__ int    g_fix_rows[NV * NN];
__device__ double g_accum;

// ---- helpers ----
__device__ __forceinline__ uint32_t smem_u32(const void* p) {
    uint32_t a;
    asm("{ .reg .u64 t; cvta.to.shared.u64 t, %1; cvt.u32.u64 %0, t; }" : "=r"(a) : "l"(p));
    return a;
}
__device__ __forceinline__ void cpa16(uint32_t dst, const void* src) {
    asm volatile("cp.async.cg.shared.global [%0], [%1], 16;" :: "r"(dst), "l"(src));
}
#define CP_COMMIT() asm volatile("cp.async.commit_group;" ::: "memory")
#define CP_WAIT1()  asm volatile("cp.async.wait_group 1;" ::: "memory")
#define CP_WAIT0()  asm volatile("cp.async.wait_group 0;" ::: "memory")
__device__ __forceinline__ uint32_t lds32(uint32_t a) {
    uint32_t v; asm volatile("ld.shared.b32 %0, [%1];" : "=r"(v) : "r"(a)); return v;
}
__device__ __forceinline__ void mma16816(float* c, const uint32_t* a, const uint32_t* b) {
    asm volatile("mma.sync.aligned.m16n8k16.row.col.f32.f16.f16.f32 "
        "{%0,%1,%2,%3}, {%4,%5,%6,%7}, {%8,%9}, {%0,%1,%2,%3};"
        : "+f"(c[0]), "+f"(c[1]), "+f"(c[2]), "+f"(c[3])
        : "r"(a[0]), "r"(a[1]), "r"(a[2]), "r"(a[3]), "r"(b[0]), "r"(b[1]));
}
__device__ __forceinline__ void ins3(float v, int i, float* a, int* ai) {
    if (v < a[0] || (v == a[0] && i < ai[0])) {
        a[2] = a[1]; ai[2] = ai[1]; a[1] = a[0]; ai[1] = ai[0]; a[0] = v; ai[0] = i;
    } else if (v < a[1] || (v == a[1] && i < ai[1])) {
        a[2] = a[1]; ai[2] = ai[1]; a[1] = v; ai[1] = i;
    } else if (v < a[2] || (v == a[2] && i < ai[2])) {
        a[2] = v; ai[2] = i;
    }
}

// ---- prep: transpose E -> g_Wt fp32 + g_Wh fp16 (fused) ----
__global__ void transpose_kernel(const float* __restrict__ E) {
    __shared__ float t[32][33];
    int v = blockIdx.z, k0 = blockIdx.x * 32, d0 = blockIdx.y * 32;
    int tx = threadIdx.x, ty = threadIdx.y;
    const float* Ev = E + (size_t)v * ND * NK;
    #pragma unroll
    for (int j = 0; j < 32; j += 8) t[ty + j][tx] = Ev[(size_t)(d0 + ty + j) * NK + k0 + tx];
    __syncthreads();
    float* Wv = g_Wt + (size_t)v * NK * ND;
    __half* Hv = g_Wh + (size_t)v * NK * ND;
    #pragma unroll
    for (int j = 0; j < 32; j += 8) {
        float val = t[tx][ty + j];
        size_t o = (size_t)(k0 + ty + j) * ND + d0 + tx;
        Wv[o] = val;
        Hv[o] = __float2half_rn(val);
    }
}

// ---- prep: ||w||^2 from transposed Wt (coalesced, warp per row) ----
__global__ void wsq_kernel() {
    int row = blockIdx.x * 8 + (threadIdx.x >> 5);   // 0..16383
    int lane = threadIdx.x & 31;
    const float* p = g_Wt + (size_t)row * ND + lane * 8;
    float4 a = *(const float4*)p;
    float4 b = *(const float4*)(p + 4);
    double s = (double)a.x * a.x + (double)a.y * a.y + (double)a.z * a.z + (double)a.w * a.w
             + (double)b.x * b.x + (double)b.y * b.y + (double)b.z * b.z + (double)b.w * b.w;
    #pragma unroll
    for (int off = 16; off > 0; off >>= 1) s += __shfl_down_sync(0xFFFFFFFFu, s, off);
    if (lane == 0) g_wsq[row] = (float)s;
    if (blockIdx.x == 0 && threadIdx.x == 0) { g_accum = 0.0; g_fix_count = 0; }
}

__global__ void convertX_kernel(const float* __restrict__ X) {
    size_t i2 = ((size_t)blockIdx.x * 256 + threadIdx.x) * 2;
    float2 x = *(const float2*)(X + i2);
    *(__half2*)(&g_Xh[i2]) = __floats2half2_rn(x.x, x.y);
}

// ---- exact fp64 score ----
__device__ double dscore(const float* __restrict__ xrow, const float* __restrict__ Ev, int k) {
    const float* wc = Ev + k;
    double dot = 0.0, ws = 0.0;
    #pragma unroll 4
    for (int d = 0; d < ND; ++d) {
        double w = (double)wc[(size_t)d * NK];
        dot += (double)xrow[d] * w;
        ws  += w * w;
    }
    return ws - 2.0 * dot;
}

// ---- main: fp16 HMMA + top-3 + windowed adjudication ----
// grid (NN/64, NV), 256 thr = 8 warps (2M x 4N), warp tile 32x32, 2 CTAs/SM
__global__ void __launch_bounds__(256, 2)
gemm_argmin_kernel(const float* __restrict__ X, const float* __restrict__ E) {
    extern __shared__ char smem[];
    const uint32_t sb = smem_u32(smem);
    const int tid = threadIdx.x, lane = tid & 31, wid = tid >> 5;
    const int wm = wid & 1, wn = wid >> 1;        // 2M x 4N
    const int g = lane >> 2, tg = lane & 3;
    const int v = blockIdx.y, row0 = blockIdx.x * 64;

    {
        float* sw = (float*)(smem + WSQ_S);
        #pragma unroll
        for (int q = 0; q < 4; ++q) sw[tid + q * 256] = g_wsq[v * NK + tid + q * 256];
    }

    const size_t abase = ((size_t)v * NN + row0) * ND;

    // A: all 4 d-tiles resident (one cp.async group)
    {
        #pragma unroll
        for (int j = 0; j < 8; ++j) {
            int q = tid + j * 256;                // 0..2047 16B-chunks
            int dc = q >> 9, r = (q >> 3) & 63, c = q & 7;
            cpa16(sb + AOFF + dc * ATILB + r * ROWB + c * 16,
                  (const char*)g_Xh + (abase + (size_t)r * ND + dc * 64 + c * 8) * 2);
        }
        CP_COMMIT();
    }

    // B issue for phase i (i = nc*4 + dc), ring buffer i % 3; chunk = 128 rows x 64 d
    auto issueB = [&](int i) {
        int nc = i >> 2, dc = i & 3, buf = i % 3;
        size_t bb = ((size_t)v * NK + nc * 128) * ND + dc * 64;
        #pragma unroll
        for (int j = 0; j < 4; ++j) {
            int q = tid * 4 + j;                  // 0..1023 16B-chunks
            int r = q >> 3, c = q & 7;
            cpa16(sb + BOFF + buf * BTILB + r * ROWB + c * 16,
                  (const char*)g_Wh + (bb + (size_t)r * ND + c * 8) * 2);
        }
        CP_COMMIT();
    };

    float tv[4][3]; int ti[4][3];
    #pragma unroll
    for (int s = 0; s < 4; ++s)
        #pragma unroll
        for (int j = 0; j < 3; ++j) { tv[s][j] = FLT_MAX; ti[s][j] = 0x7FFFFFFF; }

    issueB(0);
    issueB(1);
    const float* sw = (const float*)(smem + WSQ_S);

    for (int nc = 0; nc < 8; ++nc) {
        float c[2][4][4];
        #pragma unroll
        for (int mf = 0; mf < 2; ++mf)
            #pragma unroll
            for (int nf = 0; nf < 4; ++nf)
                #pragma unroll
                for (int e = 0; e < 4; ++e) c[mf][nf][e] = 0.0f;

        for (int dc = 0; dc < 4; ++dc) {
            int ph = nc * 4 + dc;
            if (ph < 31) { CP_WAIT1(); } else { CP_WAIT0(); }
            __syncthreads();                       // prev reads done + this phase data visible
            if (ph < 30) issueB(ph + 2);           // ring slot consumed 2 phases ago

            const uint32_t Ab = sb + AOFF + dc * ATILB;
            const uint32_t Bb = sb + BOFF + (ph % 3) * BTILB;
            #pragma unroll
            for (int ks = 0; ks < 4; ++ks) {
                const uint32_t kb = ks * 32 + tg * 4;
                uint32_t A[2][4];
                #pragma unroll
                for (int mf = 0; mf < 2; ++mf) {
                    uint32_t ra = Ab + (wm * 32 + mf * 16 + g) * ROWB + kb;
                    A[mf][0] = lds32(ra);       A[mf][1] = lds32(ra + 8 * ROWB);
                    A[mf][2] = lds32(ra + 16);  A[mf][3] = lds32(ra + 8 * ROWB + 16);
                }
                uint32_t B[4][2];
                #pragma unroll
                for (int nf = 0; nf < 4; ++nf) {
                    uint32_t rb = Bb + (wn * 32 + nf * 8 + g) * ROWB + kb;
                    B[nf][0] = lds32(rb); B[nf][1] = lds32(rb + 16);
                }
                #pragma unroll
                for (int mf = 0; mf < 2; ++mf)
                    #pragma unroll
                    for (int nf = 0; nf < 4; ++nf) mma16816(c[mf][nf], A[mf], B[nf]);
            }
        }

        // score this 128-col chunk
        #pragma unroll
        for (int mf = 0; mf < 2; ++mf)
            #pragma unroll
            for (int nf = 0; nf < 4; ++nf)
                #pragma unroll
                for (int e = 0; e < 4; ++e) {
                    int col  = nc * 128 + wn * 32 + nf * 8 + tg * 2 + (e & 1);
                    int slot = mf * 2 + (e >> 1);
                    float sc = sw[col] - 2.0f * c[mf][nf][e];
                    float* a = tv[slot]; int* ai = ti[slot];
                    if (sc < a[2]) {
                        if (sc < a[1]) {
                            a[2] = a[1]; ai[2] = ai[1];
                            if (sc < a[0]) { a[1] = a[0]; ai[1] = ai[0]; a[0] = sc; ai[0] = col; }
                            else           { a[1] = sc; ai[1] = col; }
                        } else { a[2] = sc; ai[2] = col; }
                    }
                }
    }

    // merge top-3 across the 4 lanes (tg) sharing each row
    const unsigned m = 0xFFFFFFFFu;
    #pragma unroll
    for (int off = 1; off < 4; off <<= 1) {
        #pragma unroll
        for (int s = 0; s < 4; ++s) {
            float ov[3]; int oi[3];
            #pragma unroll
            for (int j = 0; j < 3; ++j) {
                ov[j] = __shfl_xor_sync(m, tv[s][j], off);
                oi[j] = __shfl_xor_sync(m, ti[s][j], off);
            }
            #pragma unroll
            for (int j = 0; j < 3; ++j) ins3(ov[j], oi[j], tv[s], ti[s]);
        }
    }

    float* mv = (float*)(smem + MRG);          // [4][64][3]
    int*   mi = (int*)  (smem + MRG + 3072);
    __syncthreads();                            // all phases done before merge reuse
    if (tg == 0) {
        #pragma unroll
        for (int s = 0; s < 4; ++s) {
            int rl = wm * 32 + (s >> 1) * 16 + g + (s & 1) * 8;   // 0..63
            #pragma unroll
            for (int j = 0; j < 3; ++j) {
                mv[(wn * 64 + rl) * 3 + j] = tv[s][j];
                mi[(wn * 64 + rl) * 3 + j] = ti[s][j];
            }
        }
    }
    __syncthreads();

    if (tid < 64) {
        float a[3]; int ai[3];
        #pragma unroll
        for (int j = 0; j < 3; ++j) { a[j] = mv[tid * 3 + j]; ai[j] = mi[tid * 3 + j]; }
        #pragma unroll
        for (int grp = 1; grp < 4; ++grp)
            #pragma unroll
            for (int j = 0; j < 3; ++j)
                ins3(mv[(grp * 64 + tid) * 3 + j], mi[(grp * 64 + tid) * 3 + j], a, ai);

        int grow = row0 + tid, kk = ai[0];
        float gap2 = a[1] - a[0], gap3 = a[2] - a[0];
        if (gap3 < W1) {
            int slot = atomicAdd(&g_fix_count, 1);
            g_fix_rows[slot] = v * NN + grow;          // full exact rescore later
        } else if (gap2 < W1) {
            const float* xrow = X + ((size_t)v * NN + grow) * ND;
            const float* Ev = E + (size_t)v * ND * NK;
            double sb2 = dscore(xrow, Ev, ai[0]);
            double ss2 = dscore(xrow, Ev, ai[1]);
            if (ss2 < sb2 || (ss2 == sb2 && ai[1] < ai[0])) kk = ai[1];
        }
        g_idx[v * NN + grow] = kk;
    }
}

// ---- exact full-row rescore for flagged rows ----
__global__ void __launch_bounds__(256)
fix_kernel(const float* __restrict__ X, const float* __restrict__ E) {
    __shared__ float xs[ND];
    __shared__ float wv[16];
    __shared__ int   wi[16];
    int cnt = g_fix_count;
    for (int f = blockIdx.x; f < cnt; f += gridDim.x) {
        int R = g_fix_rows[f];
        int v = R >> 13;
        __syncthreads();
        xs[threadIdx.x] = X[(size_t)R * ND + threadIdx.x];
        __syncthreads();

        float b = FLT_MAX, s = FLT_MAX; int bi = 0x7FFFFFFF, si = 0x7FFFFFFF;
        #pragma unroll
        for (int kk = 0; kk < 4; ++kk) {
            int k = threadIdx.x * 4 + kk;
            const float* w = g_Wt + ((size_t)v * NK + k) * ND;
            float dot = 0.0f;
            #pragma unroll 8
            for (int d = 0; d < ND; ++d) dot = fmaf(xs[d], w[d], dot);
            float sc = g_wsq[v * NK + k] - 2.0f * dot;
            if (sc < b || (sc == b && k < bi)) { s = b; si = bi; b = sc; bi = k; }
            else if (sc < s || (sc == s && k < si)) { s = sc; si = k; }
        }
        const unsigned m = 0xFFFFFFFFu;
        #pragma unroll
        for (int off = 1; off < 32; off <<= 1) {
            float ob = __shfl_xor_sync(m, b, off);  int obi = __shfl_xor_sync(m, bi, off);
            float os = __shfl_xor_sync(m, s, off);  int osi = __shfl_xor_sync(m, si, off);
            bool tko = (ob < b) || (ob == b && obi < bi);
            float lb = tko ? b : ob; int lbi = tko ? bi : obi;
            float ws_ = tko ? os : s; int wsi = tko ? osi : si;
            if (tko) { b = ob; bi = obi; }
            if (ws_ < lb || (ws_ == lb && wsi < lbi)) { s = ws_; si = wsi; }
            else                                      { s = lb;  si = lbi; }
        }
        int wrp = threadIdx.x >> 5;
        if ((threadIdx.x & 31) == 0) { wv[wrp * 2] = b; wv[wrp * 2 + 1] = s; wi[wrp * 2] = bi; wi[wrp * 2 + 1] = si; }
        __syncthreads();
        if (threadIdx.x == 0) {
            float B = FLT_MAX, S = FLT_MAX; int Bi = 0x7FFFFFFF, Si = 0x7FFFFFFF;
            for (int q = 0; q < 16; ++q) {
                float vq = wv[q]; int iq = wi[q];
                if (vq < B || (vq == B && iq < Bi)) { S = B; Si = Bi; B = vq; Bi = iq; }
                else if (vq < S || (vq == S && iq < Si)) { S = vq; Si = iq; }
            }
            int kk = Bi;
            if (S - B < MARGIN) {
                const float* Ev = E + (size_t)v * ND * NK;
                double sb2 = dscore(xs, Ev, Bi);
                double ss2 = dscore(xs, Ev, Si);
                if (ss2 < sb2 || (ss2 == sb2 && Si < Bi)) kk = Si;
            }
            g_idx[R] = kk;
        }
        __syncthreads();
    }
}

// ---- gather + loss ----
__global__ void __launch_bounds__(256)
gather_kernel(const float* __restrict__ X, float* __restrict__ out) {
    int R = blockIdx.x * 4 + (threadIdx.x >> 6);
    int lane64 = threadIdx.x & 63;
    int k = g_idx[R];
    int v = R >> 13;
    float4 qv = ((const float4*)(g_Wt + ((size_t)v * NK + k) * ND))[lane64];
    float4 xv = ((const float4*)(X + (size_t)R * ND))[lane64];
    ((float4*)(out + (size_t)R * ND))[lane64] = qv;

    float dx = qv.x - xv.x, dy = qv.y - xv.y, dz = qv.z - xv.z, dw = qv.w - xv.w;
    float s = dx * dx + dy * dy + dz * dz + dw * dw;
    #pragma unroll
    for (int off = 16; off > 0; off >>= 1) s += __shfl_down_sync(0xFFFFFFFFu, s, off);

    __shared__ float ps[8];
    int w = threadIdx.x >> 5, l = threadIdx.x & 31;
    if (l == 0) ps[w] = s;
    __syncthreads();
    if (threadIdx.x == 0) {
        float tot = 0.0f;
        #pragma unroll
        for (int i = 0; i < 8; ++i) tot += ps[i];
        atomicAdd(&g_accum, (double)tot);
    }
}

__global__ void loss_kernel(float* __restrict__ out, long long out_size) {
    const long long VND = (long long)NV * NN * ND;
    double loss = 1.25 * g_accum / (double)VND;
    for (long long i = VND + threadIdx.x; i < out_size; i += blockDim.x)
        out[i] = (float)loss;
}

extern "C" void kernel_launch(void* const* d_in, const int* in_sizes, int n_in,
                              void* d_out, int out_size) {
    const float* X = (const float*)d_in[0];
    const float* E = (const float*)d_in[1];
    float* out = (float*)d_out;

    cudaFuncSetAttribute((const void*)gemm_argmin_kernel,
                         cudaFuncAttributeMaxDynamicSharedMemorySize, SMEM_TOTAL);

    transpose_kernel<<<dim3(NK / 32, ND / 32, NV), dim3(32, 8)>>>(E);
    wsq_kernel<<<2048, 256>>>();
    convertX_kernel<<<65536, 256>>>(X);
    gemm_argmin_kernel<<<dim3(NN / 64, NV), 256, SMEM_TOTAL>>>(X, E);
    fix_kernel<<<1024, 256>>>(X, E);
    gather_kernel<<<(NV * NN) / 4, 256>>>(X, out);
    loss_kernel<<<1, 32>>>(out, (long long)out_size);
}

// round 10
// speedup vs baseline: 1.2133x; 1.2133x over previous
#include <cuda_runtime.h>
#include <cuda_fp16.h>
#include <cfloat>
#include <cstdint>

#define NV 16
#define NN 8192
#define ND 256
#define NK 1024
#define W1 0.26f          // coarse-score uncertainty window
#define MARGIN 0.05f      // fp32-exact pair-adjudication margin

// ---- smem layout (bytes) ----
// A resident: 4 d-tiles x (128 rows x 144B) = 73728
// B ring:     3 bufs   x (64 rows x 144B)   = 27648
#define ROWB   144
#define ATILB  18432
#define BTILB  9216
#define AOFF   0
#define BOFF   73728
#define WSQ_S  101376
#define MRG    105472         // 2 n-groups x 128 x 3 x (4+4)B = 6144
#define SMEM_TOTAL 111616

// ---- device scratch ----
__device__ float  g_wsq[NV * NK];
__device__ float  g_Wt[(size_t)NV * NK * ND];                    // [V][K][D] fp32
__device__ __align__(256) __half g_Xh[(size_t)NV * NN * ND];     // X fp16
__device__ __align__(256) __half g_Wh[(size_t)NV * NK * ND];     // Wt fp16
__device__ int    g_idx[NV * NN];
__device__ int    g_fix_count;
__device__ int    g_fix_rows[NV * NN];
__device__ double g_accum;

// ---- helpers ----
__device__ __forceinline__ uint32_t smem_u32(const void* p) {
    uint32_t a;
    asm("{ .reg .u64 t; cvta.to.shared.u64 t, %1; cvt.u32.u64 %0, t; }" : "=r"(a) : "l"(p));
    return a;
}
__device__ __forceinline__ void cpa16(uint32_t dst, const void* src) {
    asm volatile("cp.async.cg.shared.global [%0], [%1], 16;" :: "r"(dst), "l"(src));
}
#define CP_COMMIT() asm volatile("cp.async.commit_group;" ::: "memory")
#define CP_WAIT1()  asm volatile("cp.async.wait_group 1;" ::: "memory")
#define CP_WAIT0()  asm volatile("cp.async.wait_group 0;" ::: "memory")
__device__ __forceinline__ void ldsm4(uint32_t* r, uint32_t a) {
    asm volatile("ldmatrix.sync.aligned.m8n8.x4.shared.b16 {%0,%1,%2,%3}, [%4];"
        : "=r"(r[0]), "=r"(r[1]), "=r"(r[2]), "=r"(r[3]) : "r"(a));
}
__device__ __forceinline__ void mma16816(float* c, const uint32_t* a, const uint32_t* b) {
    asm volatile("mma.sync.aligned.m16n8k16.row.col.f32.f16.f16.f32 "
        "{%0,%1,%2,%3}, {%4,%5,%6,%7}, {%8,%9}, {%0,%1,%2,%3};"
        : "+f"(c[0]), "+f"(c[1]), "+f"(c[2]), "+f"(c[3])
        : "r"(a[0]), "r"(a[1]), "r"(a[2]), "r"(a[3]), "r"(b[0]), "r"(b[1]));
}
__device__ __forceinline__ void ins3(float v, int i, float* a, int* ai) {
    if (v < a[0] || (v == a[0] && i < ai[0])) {
        a[2] = a[1]; ai[2] = ai[1]; a[1] = a[0]; ai[1] = ai[0]; a[0] = v; ai[0] = i;
    } else if (v < a[1] || (v == a[1] && i < ai[1])) {
        a[2] = a[1]; ai[2] = ai[1]; a[1] = v; ai[1] = i;
    } else if (v < a[2] || (v == a[2] && i < ai[2])) {
        a[2] = v; ai[2] = i;
    }
}

// ---- prep: transpose E -> g_Wt fp32 + g_Wh fp16 (fused) ----
__global__ void transpose_kernel(const float* __restrict__ E) {
    __shared__ float t[32][33];
    int v = blockIdx.z, k0 = blockIdx.x * 32, d0 = blockIdx.y * 32;
    int tx = threadIdx.x, ty = threadIdx.y;
    const float* Ev = E + (size_t)v * ND * NK;
    #pragma unroll
    for (int j = 0; j < 32; j += 8) t[ty + j][tx] = Ev[(size_t)(d0 + ty + j) * NK + k0 + tx];
    __syncthreads();
    float* Wv = g_Wt + (size_t)v * NK * ND;
    __half* Hv = g_Wh + (size_t)v * NK * ND;
    #pragma unroll
    for (int j = 0; j < 32; j += 8) {
        float val = t[tx][ty + j];
        size_t o = (size_t)(k0 + ty + j) * ND + d0 + tx;
        Wv[o] = val;
        Hv[o] = __float2half_rn(val);
    }
}

// ---- prep: ||w||^2 from transposed Wt (coalesced, warp per row) ----
__global__ void wsq_kernel() {
    int row = blockIdx.x * 8 + (threadIdx.x >> 5);   // 0..16383
    int lane = threadIdx.x & 31;
    const float* p = g_Wt + (size_t)row * ND + lane * 8;
    float4 a = *(const float4*)p;
    float4 b = *(const float4*)(p + 4);
    double s = (double)a.x * a.x + (double)a.y * a.y + (double)a.z * a.z + (double)a.w * a.w
             + (double)b.x * b.x + (double)b.y * b.y + (double)b.z * b.z + (double)b.w * b.w;
    #pragma unroll
    for (int off = 16; off > 0; off >>= 1) s += __shfl_down_sync(0xFFFFFFFFu, s, off);
    if (lane == 0) g_wsq[row] = (float)s;
    if (blockIdx.x == 0 && threadIdx.x == 0) { g_accum = 0.0; g_fix_count = 0; }
}

__global__ void convertX_kernel(const float* __restrict__ X) {
    size_t i2 = ((size_t)blockIdx.x * 256 + threadIdx.x) * 2;
    float2 x = *(const float2*)(X + i2);
    *(__half2*)(&g_Xh[i2]) = __floats2half2_rn(x.x, x.y);
}

// ---- exact fp64 score ----
__device__ double dscore(const float* __restrict__ xrow, const float* __restrict__ Ev, int k) {
    const float* wc = Ev + k;
    double dot = 0.0, ws = 0.0;
    #pragma unroll 4
    for (int d = 0; d < ND; ++d) {
        double w = (double)wc[(size_t)d * NK];
        dot += (double)xrow[d] * w;
        ws  += w * w;
    }
    return ws - 2.0 * dot;
}

// ---- main: fp16 HMMA (ldmatrix) + top-3 + windowed adjudication ----
// grid (NN/128, NV), 256 thr = 8 warps (4M x 2N), warp tile 32x32, 2 CTAs/SM
__global__ void __launch_bounds__(256, 2)
gemm_argmin_kernel(const float* __restrict__ X, const float* __restrict__ E) {
    extern __shared__ char smem[];
    const uint32_t sb = smem_u32(smem);
    const int tid = threadIdx.x, lane = tid & 31, wid = tid >> 5;
    const int wm = wid & 3, wn = wid >> 2;        // 4M x 2N
    const int g = lane >> 2, tg = lane & 3;
    const int v = blockIdx.y, row0 = blockIdx.x * 128;

    {
        float* sw = (float*)(smem + WSQ_S);
        #pragma unroll
        for (int q = 0; q < 4; ++q) sw[tid + q * 256] = g_wsq[v * NK + tid + q * 256];
    }

    const size_t abase = ((size_t)v * NN + row0) * ND;

    // A: all 4 d-tiles resident (one cp.async group)
    {
        #pragma unroll
        for (int j = 0; j < 16; ++j) {
            int q = tid + j * 256;                // 0..4095 16B-chunks
            int dc = q >> 10, r = (q >> 3) & 127, c = q & 7;
            cpa16(sb + AOFF + dc * ATILB + r * ROWB + c * 16,
                  (const char*)g_Xh + (abase + (size_t)r * ND + dc * 64 + c * 8) * 2);
        }
        CP_COMMIT();
    }

    // B issue for phase i (i = nc*4 + dc), ring buffer i % 3; chunk = 64 rows x 64 d
    auto issueB = [&](int i) {
        int nc = i >> 2, dc = i & 3, buf = i % 3;
        size_t bb = ((size_t)v * NK + nc * 64) * ND + dc * 64;
        #pragma unroll
        for (int j = 0; j < 2; ++j) {
            int q = tid * 2 + j;                  // 0..511 16B-chunks
            int r = q >> 3, c = q & 7;
            cpa16(sb + BOFF + buf * BTILB + r * ROWB + c * 16,
                  (const char*)g_Wh + (bb + (size_t)r * ND + c * 8) * 2);
        }
        CP_COMMIT();
    };

    float tv[4][3]; int ti[4][3];
    #pragma unroll
    for (int s = 0; s < 4; ++s)
        #pragma unroll
        for (int j = 0; j < 3; ++j) { tv[s][j] = FLT_MAX; ti[s][j] = 0x7FFFFFFF; }

    issueB(0);
    issueB(1);
    const float* sw = (const float*)(smem + WSQ_S);

    // ldmatrix lane-address components (row/col pattern constant across phases)
    const uint32_t aLane = (uint32_t)((wm * 32 + (lane & 15)) * ROWB + ((lane >> 4) << 4));
    const uint32_t bLane = (uint32_t)((wn * 32 + ((lane >> 4) << 3) + (lane & 7)) * ROWB
                                      + (((lane >> 3) & 1) << 4));

    for (int nc = 0; nc < 16; ++nc) {
        float c[2][4][4];
        #pragma unroll
        for (int mf = 0; mf < 2; ++mf)
            #pragma unroll
            for (int nf = 0; nf < 4; ++nf)
                #pragma unroll
                for (int e = 0; e < 4; ++e) c[mf][nf][e] = 0.0f;

        for (int dc = 0; dc < 4; ++dc) {
            int ph = nc * 4 + dc;
            if (ph < 63) { CP_WAIT1(); } else { CP_WAIT0(); }
            __syncthreads();                       // prev reads done + this phase data visible
            if (ph < 62) issueB(ph + 2);           // ring slot consumed 2 phases ago

            const uint32_t aB = sb + AOFF + dc * ATILB + aLane;
            const uint32_t bB = sb + BOFF + (ph % 3) * BTILB + bLane;
            #pragma unroll
            for (int ks = 0; ks < 4; ++ks) {
                uint32_t A0[4], A1[4], B0[4], B1[4];
                ldsm4(A0, aB + ks * 32);                 // rows wm*32..+15
                ldsm4(A1, aB + 16 * ROWB + ks * 32);     // rows +16..+31
                ldsm4(B0, bB + ks * 32);                 // nf 0,1
                ldsm4(B1, bB + 16 * ROWB + ks * 32);     // nf 2,3
                mma16816(c[0][0], A0, B0);     mma16816(c[0][1], A0, B0 + 2);
                mma16816(c[0][2], A0, B1);     mma16816(c[0][3], A0, B1 + 2);
                mma16816(c[1][0], A1, B0);     mma16816(c[1][1], A1, B0 + 2);
                mma16816(c[1][2], A1, B1);     mma16816(c[1][3], A1, B1 + 2);
            }
        }

        // score this 64-col chunk
        #pragma unroll
        for (int mf = 0; mf < 2; ++mf)
            #pragma unroll
            for (int nf = 0; nf < 4; ++nf)
                #pragma unroll
                for (int e = 0; e < 4; ++e) {
                    int col  = nc * 64 + wn * 32 + nf * 8 + tg * 2 + (e & 1);
                    int slot = mf * 2 + (e >> 1);
                    float sc = sw[col] - 2.0f * c[mf][nf][e];
                    float* a = tv[slot]; int* ai = ti[slot];
                    if (sc < a[2]) {
                        if (sc < a[1]) {
                            a[2] = a[1]; ai[2] = ai[1];
                            if (sc < a[0]) { a[1] = a[0]; ai[1] = ai[0]; a[0] = sc; ai[0] = col; }
                            else           { a[1] = sc; ai[1] = col; }
                        } else { a[2] = sc; ai[2] = col; }
                    }
                }
    }

    // merge top-3 across the 4 lanes (tg) sharing each row
    const unsigned m = 0xFFFFFFFFu;
    #pragma unroll
    for (int off = 1; off < 4; off <<= 1) {
        #pragma unroll
        for (int s = 0; s < 4; ++s) {
            float ov[3]; int oi[3];
            #pragma unroll
            for (int j = 0; j < 3; ++j) {
                ov[j] = __shfl_xor_sync(m, tv[s][j], off);
                oi[j] = __shfl_xor_sync(m, ti[s][j], off);
            }
            #pragma unroll
            for (int j = 0; j < 3; ++j) ins3(ov[j], oi[j], tv[s], ti[s]);
        }
    }

    float* mv = (float*)(smem + MRG);          // [2][128][3]
    int*   mi = (int*)  (smem + MRG + 3072);
    __syncthreads();                            // all phases done before merge reuse
    if (tg == 0) {
        #pragma unroll
        for (int s = 0; s < 4; ++s) {
            int rl = wm * 32 + (s >> 1) * 16 + g + (s & 1) * 8;
            #pragma unroll
            for (int j = 0; j < 3; ++j) {
                mv[(wn * 128 + rl) * 3 + j] = tv[s][j];
                mi[(wn * 128 + rl) * 3 + j] = ti[s][j];
            }
        }
    }
    __syncthreads();

    if (tid < 128) {
        float a[3]; int ai[3];
        #pragma unroll
        for (int j = 0; j < 3; ++j) { a[j] = mv[tid * 3 + j]; ai[j] = mi[tid * 3 + j]; }
        #pragma unroll
        for (int j = 0; j < 3; ++j)
            ins3(mv[(128 + tid) * 3 + j], mi[(128 + tid) * 3 + j], a, ai);

        int grow = row0 + tid, kk = ai[0];
        float gap2 = a[1] - a[0], gap3 = a[2] - a[0];
        if (gap3 < W1) {
            int slot = atomicAdd(&g_fix_count, 1);
            g_fix_rows[slot] = v * NN + grow;          // full exact rescore later
        } else if (gap2 < W1) {
            const float* xrow = X + ((size_t)v * NN + grow) * ND;
            const float* Ev = E + (size_t)v * ND * NK;
            double sb2 = dscore(xrow, Ev, ai[0]);
            double ss2 = dscore(xrow, Ev, ai[1]);
            if (ss2 < sb2 || (ss2 == sb2 && ai[1] < ai[0])) kk = ai[1];
        }
        g_idx[v * NN + grow] = kk;
    }
}

// ---- exact full-row rescore for flagged rows ----
__global__ void __launch_bounds__(256)
fix_kernel(const float* __restrict__ X, const float* __restrict__ E) {
    __shared__ float xs[ND];
    __shared__ float wv[16];
    __shared__ int   wi[16];
    int cnt = g_fix_count;
    for (int f = blockIdx.x; f < cnt; f += gridDim.x) {
        int R = g_fix_rows[f];
        int v = R >> 13;
        __syncthreads();
        xs[threadIdx.x] = X[(size_t)R * ND + threadIdx.x];
        __syncthreads();

        float b = FLT_MAX, s = FLT_MAX; int bi = 0x7FFFFFFF, si = 0x7FFFFFFF;
        #pragma unroll
        for (int kk = 0; kk < 4; ++kk) {
            int k = threadIdx.x * 4 + kk;
            const float* w = g_Wt + ((size_t)v * NK + k) * ND;
            float dot = 0.0f;
            #pragma unroll 8
            for (int d = 0; d < ND; ++d) dot = fmaf(xs[d], w[d], dot);
            float sc = g_wsq[v * NK + k] - 2.0f * dot;
            if (sc < b || (sc == b && k < bi)) { s = b; si = bi; b = sc; bi = k; }
            else if (sc < s || (sc == s && k < si)) { s = sc; si = k; }
        }
        const unsigned m = 0xFFFFFFFFu;
        #pragma unroll
        for (int off = 1; off < 32; off <<= 1) {
            float ob = __shfl_xor_sync(m, b, off);  int obi = __shfl_xor_sync(m, bi, off);
            float os = __shfl_xor_sync(m, s, off);  int osi = __shfl_xor_sync(m, si, off);
            bool tko = (ob < b) || (ob == b && obi < bi);
            float lb = tko ? b : ob; int lbi = tko ? bi : obi;
            float ws_ = tko ? os : s; int wsi = tko ? osi : si;
            if (tko) { b = ob; bi = obi; }
            if (ws_ < lb || (ws_ == lb && wsi < lbi)) { s = ws_; si = wsi; }
            else                                      { s = lb;  si = lbi; }
        }
        int wrp = threadIdx.x >> 5;
        if ((threadIdx.x & 31) == 0) { wv[wrp * 2] = b; wv[wrp * 2 + 1] = s; wi[wrp * 2] = bi; wi[wrp * 2 + 1] = si; }
        __syncthreads();
        if (threadIdx.x == 0) {
            float B = FLT_MAX, S = FLT_MAX; int Bi = 0x7FFFFFFF, Si = 0x7FFFFFFF;
            for (int q = 0; q < 16; ++q) {
                float vq = wv[q]; int iq = wi[q];
                if (vq < B || (vq == B && iq < Bi)) { S = B; Si = Bi; B = vq; Bi = iq; }
                else if (vq < S || (vq == S && iq < Si)) { S = vq; Si = iq; }
            }
            int kk = Bi;
            if (S - B < MARGIN) {
                const float* Ev = E + (size_t)v * ND * NK;
                double sb2 = dscore(xs, Ev, Bi);
                double ss2 = dscore(xs, Ev, Si);
                if (ss2 < sb2 || (ss2 == sb2 && Si < Bi)) kk = Si;
            }
            g_idx[R] = kk;
        }
        __syncthreads();
    }
}

// ---- gather + loss ----
__global__ void __launch_bounds__(256)
gather_kernel(const float* __restrict__ X, float* __restrict__ out) {
    int R = blockIdx.x * 4 + (threadIdx.x >> 6);
    int lane64 = threadIdx.x & 63;
    int k = g_idx[R];
    int v = R >> 13;
    float4 qv = ((const float4*)(g_Wt + ((size_t)v * NK + k) * ND))[lane64];
    float4 xv = ((const float4*)(X + (size_t)R * ND))[lane64];
    ((float4*)(out + (size_t)R * ND))[lane64] = qv;

    float dx = qv.x - xv.x, dy = qv.y - xv.y, dz = qv.z - xv.z, dw = qv.w - xv.w;
    float s = dx * dx + dy * dy + dz * dz + dw * dw;
    #pragma unroll
    for (int off = 16; off > 0; off >>= 1) s += __shfl_down_sync(0xFFFFFFFFu, s, off);

    __shared__ float ps[8];
    int w = threadIdx.x >> 5, l = threadIdx.x & 31;
    if (l == 0) ps[w] = s;
    __syncthreads();
    if (threadIdx.x == 0) {
        float tot = 0.0f;
        #pragma unroll
        for (int i = 0; i < 8; ++i) tot += ps[i];
        atomicAdd(&g_accum, (double)tot);
    }
}

__global__ void loss_kernel(float* __restrict__ out, long long out_size) {
    const long long VND = (long long)NV * NN * ND;
    double loss = 1.25 * g_accum / (double)VND;
    for (long long i = VND + threadIdx.x; i < out_size; i += blockDim.x)
        out[i] = (float)loss;
}

extern "C" void kernel_launch(void* const* d_in, const int* in_sizes, int n_in,
                              void* d_out, int out_size) {
    const float* X = (const float*)d_in[0];
    const float* E = (const float*)d_in[1];
    float* out = (float*)d_out;

    cudaFuncSetAttribute((const void*)gemm_argmin_kernel,
                         cudaFuncAttributeMaxDynamicSharedMemorySize, SMEM_TOTAL);

    transpose_kernel<<<dim3(NK / 32, ND / 32, NV), dim3(32, 8)>>>(E);
    wsq_kernel<<<2048, 256>>>();
    convertX_kernel<<<65536, 256>>>(X);
    gemm_argmin_kernel<<<dim3(NN / 128, NV), 256, SMEM_TOTAL>>>(X, E);
    fix_kernel<<<1024, 256>>>(X, E);
    gather_kernel<<<(NV * NN) / 4, 256>>>(X, out);
    loss_kernel<<<1, 32>>>(out, (long long)out_size);
}

// round 11
// speedup vs baseline: 2.2262x; 1.8348x over previous
#include <cuda_runtime.h>
#include <cuda_fp16.h>
#include <cfloat>
#include <cstdint>

#define NV 16
#define NN 8192
#define ND 256
#define NK 1024
#define W1 0.26f          // coarse-score uncertainty window
#define MARGIN 0.05f      // fp32-exact pair-adjudication margin

// ---- smem layout (bytes) ----
#define ROWB   144
#define ATILB  18432
#define BTILB  9216
#define AOFF   0
#define BOFF   73728
#define WSQ_S  101376
#define MRG    105472
#define SMEM_TOTAL 111616

// ---- device scratch ----
__device__ float  g_wsq[NV * NK];
__device__ float  g_Wt[(size_t)NV * NK * ND];                    // [V][K][D] fp32
__device__ __align__(256) __half g_Xh[(size_t)NV * NN * ND];     // X fp16
__device__ __align__(256) __half g_Wh[(size_t)NV * NK * ND];     // Wt fp16
__device__ int    g_idx[NV * NN];
__device__ int    g_fix_count;
__device__ int    g_pair_count;
__device__ int    g_fix_rows[NV * NN];
__device__ int    g_pair_rows[NV * NN];
__device__ int2   g_pair_cands[NV * NN];
__device__ double g_accum;

// ---- helpers ----
__device__ __forceinline__ uint32_t smem_u32(const void* p) {
    uint32_t a;
    asm("{ .reg .u64 t; cvta.to.shared.u64 t, %1; cvt.u32.u64 %0, t; }" : "=r"(a) : "l"(p));
    return a;
}
__device__ __forceinline__ void cpa16(uint32_t dst, const void* src) {
    asm volatile("cp.async.cg.shared.global [%0], [%1], 16;" :: "r"(dst), "l"(src));
}
#define CP_COMMIT() asm volatile("cp.async.commit_group;" ::: "memory")
#define CP_WAIT1()  asm volatile("cp.async.wait_group 1;" ::: "memory")
#define CP_WAIT0()  asm volatile("cp.async.wait_group 0;" ::: "memory")
__device__ __forceinline__ void ldsm4(uint32_t* r, uint32_t a) {
    asm volatile("ldmatrix.sync.aligned.m8n8.x4.shared.b16 {%0,%1,%2,%3}, [%4];"
        : "=r"(r[0]), "=r"(r[1]), "=r"(r[2]), "=r"(r[3]) : "r"(a));
}
__device__ __forceinline__ void mma16816(float* c, const uint32_t* a, const uint32_t* b) {
    asm volatile("mma.sync.aligned.m16n8k16.row.col.f32.f16.f16.f32 "
        "{%0,%1,%2,%3}, {%4,%5,%6,%7}, {%8,%9}, {%0,%1,%2,%3};"
        : "+f"(c[0]), "+f"(c[1]), "+f"(c[2]), "+f"(c[3])
        : "r"(a[0]), "r"(a[1]), "r"(a[2]), "r"(a[3]), "r"(b[0]), "r"(b[1]));
}
__device__ __forceinline__ void ins3(float v, int i, float* a, int* ai) {
    if (v < a[0] || (v == a[0] && i < ai[0])) {
        a[2] = a[1]; ai[2] = ai[1]; a[1] = a[0]; ai[1] = ai[0]; a[0] = v; ai[0] = i;
    } else if (v < a[1] || (v == a[1] && i < ai[1])) {
        a[2] = a[1]; ai[2] = ai[1]; a[1] = v; ai[1] = i;
    } else if (v < a[2] || (v == a[2] && i < ai[2])) {
        a[2] = v; ai[2] = i;
    }
}

// exact fp64 score from CONTIGUOUS transposed row (1 KB, not 32 KB strided)
__device__ double dscore_row(const float* __restrict__ xrow, const float* __restrict__ wrow) {
    double dot = 0.0, ws = 0.0;
    #pragma unroll 8
    for (int d = 0; d < ND; ++d) {
        double w = (double)wrow[d];
        dot += (double)xrow[d] * w;
        ws  += w * w;
    }
    return ws - 2.0 * dot;
}

// ---- prep: transpose E -> g_Wt fp32 + g_Wh fp16 (fused) ----
__global__ void transpose_kernel(const float* __restrict__ E) {
    __shared__ float t[32][33];
    int v = blockIdx.z, k0 = blockIdx.x * 32, d0 = blockIdx.y * 32;
    int tx = threadIdx.x, ty = threadIdx.y;
    const float* Ev = E + (size_t)v * ND * NK;
    #pragma unroll
    for (int j = 0; j < 32; j += 8) t[ty + j][tx] = Ev[(size_t)(d0 + ty + j) * NK + k0 + tx];
    __syncthreads();
    float* Wv = g_Wt + (size_t)v * NK * ND;
    __half* Hv = g_Wh + (size_t)v * NK * ND;
    #pragma unroll
    for (int j = 0; j < 32; j += 8) {
        float val = t[tx][ty + j];
        size_t o = (size_t)(k0 + ty + j) * ND + d0 + tx;
        Wv[o] = val;
        Hv[o] = __float2half_rn(val);
    }
}

// ---- prep: ||w||^2 from transposed Wt (coalesced, warp per row) ----
__global__ void wsq_kernel() {
    int row = blockIdx.x * 8 + (threadIdx.x >> 5);
    int lane = threadIdx.x & 31;
    const float* p = g_Wt + (size_t)row * ND + lane * 8;
    float4 a = *(const float4*)p;
    float4 b = *(const float4*)(p + 4);
    double s = (double)a.x * a.x + (double)a.y * a.y + (double)a.z * a.z + (double)a.w * a.w
             + (double)b.x * b.x + (double)b.y * b.y + (double)b.z * b.z + (double)b.w * b.w;
    #pragma unroll
    for (int off = 16; off > 0; off >>= 1) s += __shfl_down_sync(0xFFFFFFFFu, s, off);
    if (lane == 0) g_wsq[row] = (float)s;
    if (blockIdx.x == 0 && threadIdx.x == 0) { g_accum = 0.0; g_fix_count = 0; g_pair_count = 0; }
}

__global__ void convertX_kernel(const float* __restrict__ X) {
    size_t i2 = ((size_t)blockIdx.x * 256 + threadIdx.x) * 2;
    float2 x = *(const float2*)(X + i2);
    *(__half2*)(&g_Xh[i2]) = __floats2half2_rn(x.x, x.y);
}

// ---- main: fp16 HMMA (ldmatrix) + top-3 classification (no fp64 here) ----
// grid (NN/128, NV), 256 thr = 8 warps (4M x 2N), warp tile 32x32, 2 CTAs/SM
__global__ void __launch_bounds__(256, 2)
gemm_argmin_kernel() {
    extern __shared__ char smem[];
    const uint32_t sb = smem_u32(smem);
    const int tid = threadIdx.x, lane = tid & 31, wid = tid >> 5;
    const int wm = wid & 3, wn = wid >> 2;
    const int g = lane >> 2, tg = lane & 3;
    const int v = blockIdx.y, row0 = blockIdx.x * 128;

    {
        float* sw = (float*)(smem + WSQ_S);
        #pragma unroll
        for (int q = 0; q < 4; ++q) sw[tid + q * 256] = g_wsq[v * NK + tid + q * 256];
    }

    const size_t abase = ((size_t)v * NN + row0) * ND;

    // A: all 4 d-tiles resident
    {
        #pragma unroll
        for (int j = 0; j < 16; ++j) {
            int q = tid + j * 256;
            int dc = q >> 10, r = (q >> 3) & 127, c = q & 7;
            cpa16(sb + AOFF + dc * ATILB + r * ROWB + c * 16,
                  (const char*)g_Xh + (abase + (size_t)r * ND + dc * 64 + c * 8) * 2);
        }
        CP_COMMIT();
    }

    auto issueB = [&](int i) {
        int nc = i >> 2, dc = i & 3, buf = i % 3;
        size_t bb = ((size_t)v * NK + nc * 64) * ND + dc * 64;
        #pragma unroll
        for (int j = 0; j < 2; ++j) {
            int q = tid * 2 + j;
            int r = q >> 3, c = q & 7;
            cpa16(sb + BOFF + buf * BTILB + r * ROWB + c * 16,
                  (const char*)g_Wh + (bb + (size_t)r * ND + c * 8) * 2);
        }
        CP_COMMIT();
    };

    float tv[4][3]; int ti[4][3];
    #pragma unroll
    for (int s = 0; s < 4; ++s)
        #pragma unroll
        for (int j = 0; j < 3; ++j) { tv[s][j] = FLT_MAX; ti[s][j] = 0x7FFFFFFF; }

    issueB(0);
    issueB(1);
    const float* sw = (const float*)(smem + WSQ_S);

    const uint32_t aLane = (uint32_t)((wm * 32 + (lane & 15)) * ROWB + ((lane >> 4) << 4));
    const uint32_t bLane = (uint32_t)((wn * 32 + ((lane >> 4) << 3) + (lane & 7)) * ROWB
                                      + (((lane >> 3) & 1) << 4));

    for (int nc = 0; nc < 16; ++nc) {
        float c[2][4][4];
        #pragma unroll
        for (int mf = 0; mf < 2; ++mf)
            #pragma unroll
            for (int nf = 0; nf < 4; ++nf)
                #pragma unroll
                for (int e = 0; e < 4; ++e) c[mf][nf][e] = 0.0f;

        for (int dc = 0; dc < 4; ++dc) {
            int ph = nc * 4 + dc;
            if (ph < 63) { CP_WAIT1(); } else { CP_WAIT0(); }
            __syncthreads();
            if (ph < 62) issueB(ph + 2);

            const uint32_t aB = sb + AOFF + dc * ATILB + aLane;
            const uint32_t bB = sb + BOFF + (ph % 3) * BTILB + bLane;
            #pragma unroll
            for (int ks = 0; ks < 4; ++ks) {
                uint32_t A0[4], A1[4], B0[4], B1[4];
                ldsm4(A0, aB + ks * 32);
                ldsm4(A1, aB + 16 * ROWB + ks * 32);
                ldsm4(B0, bB + ks * 32);
                ldsm4(B1, bB + 16 * ROWB + ks * 32);
                mma16816(c[0][0], A0, B0);     mma16816(c[0][1], A0, B0 + 2);
                mma16816(c[0][2], A0, B1);     mma16816(c[0][3], A0, B1 + 2);
                mma16816(c[1][0], A1, B0);     mma16816(c[1][1], A1, B0 + 2);
                mma16816(c[1][2], A1, B1);     mma16816(c[1][3], A1, B1 + 2);
            }
        }

        #pragma unroll
        for (int mf = 0; mf < 2; ++mf)
            #pragma unroll
            for (int nf = 0; nf < 4; ++nf)
                #pragma unroll
                for (int e = 0; e < 4; ++e) {
                    int col  = nc * 64 + wn * 32 + nf * 8 + tg * 2 + (e & 1);
                    int slot = mf * 2 + (e >> 1);
                    float sc = sw[col] - 2.0f * c[mf][nf][e];
                    float* a = tv[slot]; int* ai = ti[slot];
                    if (sc < a[2]) {
                        if (sc < a[1]) {
                            a[2] = a[1]; ai[2] = ai[1];
                            if (sc < a[0]) { a[1] = a[0]; ai[1] = ai[0]; a[0] = sc; ai[0] = col; }
                            else           { a[1] = sc; ai[1] = col; }
                        } else { a[2] = sc; ai[2] = col; }
                    }
                }
    }

    const unsigned m = 0xFFFFFFFFu;
    #pragma unroll
    for (int off = 1; off < 4; off <<= 1) {
        #pragma unroll
        for (int s = 0; s < 4; ++s) {
            float ov[3]; int oi[3];
            #pragma unroll
            for (int j = 0; j < 3; ++j) {
                ov[j] = __shfl_xor_sync(m, tv[s][j], off);
                oi[j] = __shfl_xor_sync(m, ti[s][j], off);
            }
            #pragma unroll
            for (int j = 0; j < 3; ++j) ins3(ov[j], oi[j], tv[s], ti[s]);
        }
    }

    float* mv = (float*)(smem + MRG);
    int*   mi = (int*)  (smem + MRG + 3072);
    __syncthreads();
    if (tg == 0) {
        #pragma unroll
        for (int s = 0; s < 4; ++s) {
            int rl = wm * 32 + (s >> 1) * 16 + g + (s & 1) * 8;
            #pragma unroll
            for (int j = 0; j < 3; ++j) {
                mv[(wn * 128 + rl) * 3 + j] = tv[s][j];
                mi[(wn * 128 + rl) * 3 + j] = ti[s][j];
            }
        }
    }
    __syncthreads();

    if (tid < 128) {
        float a[3]; int ai[3];
        #pragma unroll
        for (int j = 0; j < 3; ++j) { a[j] = mv[tid * 3 + j]; ai[j] = mi[tid * 3 + j]; }
        #pragma unroll
        for (int j = 0; j < 3; ++j)
            ins3(mv[(128 + tid) * 3 + j], mi[(128 + tid) * 3 + j], a, ai);

        int R = v * NN + row0 + tid;
        g_idx[R] = ai[0];                          // default; fix kernels may overwrite
        float gap2 = a[1] - a[0], gap3 = a[2] - a[0];
        if (gap3 < W1) {
            int slot = atomicAdd(&g_fix_count, 1);
            g_fix_rows[slot] = R;                  // full exact rescore
        } else if (gap2 < W1) {
            int slot = atomicAdd(&g_pair_count, 1);
            g_pair_rows[slot] = R;                 // exact pair adjudication
            g_pair_cands[slot] = make_int2(ai[0], ai[1]);
        }
    }
}

// ---- exact pair adjudication: one warp per flagged row, contiguous g_Wt reads ----
__global__ void __launch_bounds__(256)
fixpair_kernel(const float* __restrict__ X) {
    int cnt = g_pair_count;
    int nw = gridDim.x * 8;
    int w = blockIdx.x * 8 + (threadIdx.x >> 5);
    int lane = threadIdx.x & 31;
    for (int e = w; e < cnt; e += nw) {
        int R = g_pair_rows[e];
        int2 cd = g_pair_cands[e];
        int v = R >> 13;
        const float* xp = X + (size_t)R * ND + lane * 8;
        double s2[2];
        #pragma unroll
        for (int c = 0; c < 2; ++c) {
            int k = c ? cd.y : cd.x;
            const float* wr = g_Wt + ((size_t)v * NK + k) * ND + lane * 8;
            double dot = 0.0, ws = 0.0;
            #pragma unroll
            for (int j = 0; j < 8; ++j) {
                double wv_ = (double)wr[j];
                dot += (double)xp[j] * wv_;
                ws  += wv_ * wv_;
            }
            double sc = ws - 2.0 * dot;
            #pragma unroll
            for (int off = 16; off > 0; off >>= 1)
                sc += __shfl_down_sync(0xFFFFFFFFu, sc, off);
            s2[c] = sc;
        }
        if (lane == 0) {
            int kk = (s2[1] < s2[0] || (s2[1] == s2[0] && cd.y < cd.x)) ? cd.y : cd.x;
            g_idx[R] = kk;
        }
    }
}

// ---- exact full-row rescore for triple-flagged rows ----
__global__ void __launch_bounds__(256)
fix_kernel(const float* __restrict__ X) {
    __shared__ float xs[ND];
    __shared__ float wv[16];
    __shared__ int   wi[16];
    int cnt = g_fix_count;
    for (int f = blockIdx.x; f < cnt; f += gridDim.x) {
        int R = g_fix_rows[f];
        int v = R >> 13;
        __syncthreads();
        xs[threadIdx.x] = X[(size_t)R * ND + threadIdx.x];
        __syncthreads();

        float b = FLT_MAX, s = FLT_MAX; int bi = 0x7FFFFFFF, si = 0x7FFFFFFF;
        #pragma unroll
        for (int kk = 0; kk < 4; ++kk) {
            int k = threadIdx.x * 4 + kk;
            const float* w = g_Wt + ((size_t)v * NK + k) * ND;
            float dot = 0.0f;
            #pragma unroll 8
            for (int d = 0; d < ND; ++d) dot = fmaf(xs[d], w[d], dot);
            float sc = g_wsq[v * NK + k] - 2.0f * dot;
            if (sc < b || (sc == b && k < bi)) { s = b; si = bi; b = sc; bi = k; }
            else if (sc < s || (sc == s && k < si)) { s = sc; si = k; }
        }
        const unsigned m = 0xFFFFFFFFu;
        #pragma unroll
        for (int off = 1; off < 32; off <<= 1) {
            float ob = __shfl_xor_sync(m, b, off);  int obi = __shfl_xor_sync(m, bi, off);
            float os = __shfl_xor_sync(m, s, off);  int osi = __shfl_xor_sync(m, si, off);
            bool tko = (ob < b) || (ob == b && obi < bi);
            float lb = tko ? b : ob; int lbi = tko ? bi : obi;
            float ws_ = tko ? os : s; int wsi = tko ? osi : si;
            if (tko) { b = ob; bi = obi; }
            if (ws_ < lb || (ws_ == lb && wsi < lbi)) { s = ws_; si = wsi; }
            else                                      { s = lb;  si = lbi; }
        }
        int wrp = threadIdx.x >> 5;
        if ((threadIdx.x & 31) == 0) { wv[wrp * 2] = b; wv[wrp * 2 + 1] = s; wi[wrp * 2] = bi; wi[wrp * 2 + 1] = si; }
        __syncthreads();
        if (threadIdx.x == 0) {
            float B = FLT_MAX, S = FLT_MAX; int Bi = 0x7FFFFFFF, Si = 0x7FFFFFFF;
            for (int q = 0; q < 16; ++q) {
                float vq = wv[q]; int iq = wi[q];
                if (vq < B || (vq == B && iq < Bi)) { S = B; Si = Bi; B = vq; Bi = iq; }
                else if (vq < S || (vq == S && iq < Si)) { S = vq; Si = iq; }
            }
            int kk = Bi;
            if (S - B < MARGIN) {
                const float* Wv_ = g_Wt + (size_t)v * NK * ND;
                double sb2 = dscore_row(xs, Wv_ + (size_t)Bi * ND);
                double ss2 = dscore_row(xs, Wv_ + (size_t)Si * ND);
                if (ss2 < sb2 || (ss2 == sb2 && Si < Bi)) kk = Si;
            }
            g_idx[R] = kk;
        }
        __syncthreads();
    }
}

// ---- gather + loss ----
__global__ void __launch_bounds__(256)
gather_kernel(const float* __restrict__ X, float* __restrict__ out) {
    int R = blockIdx.x * 4 + (threadIdx.x >> 6);
    int lane64 = threadIdx.x & 63;
    int k = g_idx[R];
    int v = R >> 13;
    float4 qv = ((const float4*)(g_Wt + ((size_t)v * NK + k) * ND))[lane64];
    float4 xv = ((const float4*)(X + (size_t)R * ND))[lane64];
    ((float4*)(out + (size_t)R * ND))[lane64] = qv;

    float dx = qv.x - xv.x, dy = qv.y - xv.y, dz = qv.z - xv.z, dw = qv.w - xv.w;
    float s = dx * dx + dy * dy + dz * dz + dw * dw;
    #pragma unroll
    for (int off = 16; off > 0; off >>= 1) s += __shfl_down_sync(0xFFFFFFFFu, s, off);

    __shared__ float ps[8];
    int w = threadIdx.x >> 5, l = threadIdx.x & 31;
    if (l == 0) ps[w] = s;
    __syncthreads();
    if (threadIdx.x == 0) {
        float tot = 0.0f;
        #pragma unroll
        for (int i = 0; i < 8; ++i) tot += ps[i];
        atomicAdd(&g_accum, (double)tot);
    }
}

__global__ void loss_kernel(float* __restrict__ out, long long out_size) {
    const long long VND = (long long)NV * NN * ND;
    double loss = 1.25 * g_accum / (double)VND;
    for (long long i = VND + threadIdx.x; i < out_size; i += blockDim.x)
        out[i] = (float)loss;
}

extern "C" void kernel_launch(void* const* d_in, const int* in_sizes, int n_in,
                              void* d_out, int out_size) {
    const float* X = (const float*)d_in[0];
    const float* E = (const float*)d_in[1];
    float* out = (float*)d_out;

    cudaFuncSetAttribute((const void*)gemm_argmin_kernel,
                         cudaFuncAttributeMaxDynamicSharedMemorySize, SMEM_TOTAL);

    transpose_kernel<<<dim3(NK / 32, ND / 32, NV), dim3(32, 8)>>>(E);
    wsq_kernel<<<2048, 256>>>();
    convertX_kernel<<<65536, 256>>>(X);
    gemm_argmin_kernel<<<dim3(NN / 128, NV), 256, SMEM_TOTAL>>>();
    fixpair_kernel<<<512, 256>>>(X);
    fix_kernel<<<1024, 256>>>(X);
    gather_kernel<<<(NV * NN) / 4, 256>>>(X, out);
    loss_kernel<<<1, 32>>>(out, (long long)out_size);
}

// round 13
// speedup vs baseline: 2.2831x; 1.0256x over previous
#include <cuda_runtime.h>
#include <cuda_fp16.h>
#include <cfloat>
#include <cstdint>

#define NV 16
#define NN 8192
#define ND 256
#define NK 1024
#define W1 0.26f          // coarse-score uncertainty window
#define MARGIN 0.05f      // fp32-exact pair-adjudication margin

// ---- smem layout (bytes) ----
#define ROWB   144
#define ATILB  18432
#define BTILB  9216
#define AOFF   0
#define BOFF   73728
#define WSQ_S  101376
#define MRG    105472
#define SMEM_TOTAL 111616

// ---- device scratch ----
__device__ float  g_wsq[NV * NK];
__device__ float  g_Wt[(size_t)NV * NK * ND];                    // [V][K][D] fp32
__device__ __align__(256) __half g_Xh[(size_t)NV * NN * ND];     // X fp16
__device__ __align__(256) __half g_Wh[(size_t)NV * NK * ND];     // Wt fp16
__device__ int    g_idx[NV * NN];
__device__ int    g_fix_count;
__device__ int    g_pair_count;
__device__ int    g_fix_rows[NV * NN];
__device__ int    g_pair_rows[NV * NN];
__device__ int2   g_pair_cands[NV * NN];
__device__ double g_accum;

// ---- helpers ----
__device__ __forceinline__ uint32_t smem_u32(const void* p) {
    uint32_t a;
    asm("{ .reg .u64 t; cvta.to.shared.u64 t, %1; cvt.u32.u64 %0, t; }" : "=r"(a) : "l"(p));
    return a;
}
__device__ __forceinline__ void cpa16(uint32_t dst, const void* src) {
    asm volatile("cp.async.cg.shared.global [%0], [%1], 16;" :: "r"(dst), "l"(src));
}
#define CP_COMMIT() asm volatile("cp.async.commit_group;" ::: "memory")
#define CP_WAIT1()  asm volatile("cp.async.wait_group 1;" ::: "memory")
#define CP_WAIT0()  asm volatile("cp.async.wait_group 0;" ::: "memory")
__device__ __forceinline__ void ldsm4(uint32_t* r, uint32_t a) {
    asm volatile("ldmatrix.sync.aligned.m8n8.x4.shared.b16 {%0,%1,%2,%3}, [%4];"
        : "=r"(r[0]), "=r"(r[1]), "=r"(r[2]), "=r"(r[3]) : "r"(a));
}
__device__ __forceinline__ void mma16816(float* c, const uint32_t* a, const uint32_t* b) {
    asm volatile("mma.sync.aligned.m16n8k16.row.col.f32.f16.f16.f32 "
        "{%0,%1,%2,%3}, {%4,%5,%6,%7}, {%8,%9}, {%0,%1,%2,%3};"
        : "+f"(c[0]), "+f"(c[1]), "+f"(c[2]), "+f"(c[3])
        : "r"(a[0]), "r"(a[1]), "r"(a[2]), "r"(a[3]), "r"(b[0]), "r"(b[1]));
}
__device__ __forceinline__ void ins3(float v, int i, float* a, int* ai) {
    if (v < a[0] || (v == a[0] && i < ai[0])) {
        a[2] = a[1]; ai[2] = ai[1]; a[1] = a[0]; ai[1] = ai[0]; a[0] = v; ai[0] = i;
    } else if (v < a[1] || (v == a[1] && i < ai[1])) {
        a[2] = a[1]; ai[2] = ai[1]; a[1] = v; ai[1] = i;
    } else if (v < a[2] || (v == a[2] && i < ai[2])) {
        a[2] = v; ai[2] = i;
    }
}

// exact fp64 score from CONTIGUOUS transposed row
__device__ double dscore_row(const float* __restrict__ xrow, const float* __restrict__ wrow) {
    double dot = 0.0, ws = 0.0;
    #pragma unroll 8
    for (int d = 0; d < ND; ++d) {
        double w = (double)wrow[d];
        dot += (double)xrow[d] * w;
        ws  += w * w;
    }
    return ws - 2.0 * dot;
}

// ---- prep: transpose E -> g_Wt fp32 + g_Wh fp16 (fused) ----
__global__ void transpose_kernel(const float* __restrict__ E) {
    __shared__ float t[32][33];
    int v = blockIdx.z, k0 = blockIdx.x * 32, d0 = blockIdx.y * 32;
    int tx = threadIdx.x, ty = threadIdx.y;
    const float* Ev = E + (size_t)v * ND * NK;
    #pragma unroll
    for (int j = 0; j < 32; j += 8) t[ty + j][tx] = Ev[(size_t)(d0 + ty + j) * NK + k0 + tx];
    __syncthreads();
    float* Wv = g_Wt + (size_t)v * NK * ND;
    __half* Hv = g_Wh + (size_t)v * NK * ND;
    #pragma unroll
    for (int j = 0; j < 32; j += 8) {
        float val = t[tx][ty + j];
        size_t o = (size_t)(k0 + ty + j) * ND + d0 + tx;
        Wv[o] = val;
        Hv[o] = __float2half_rn(val);
    }
}

// ---- prep: ||w||^2 from transposed Wt (coalesced, warp per row) ----
__global__ void wsq_kernel() {
    int row = blockIdx.x * 8 + (threadIdx.x >> 5);
    int lane = threadIdx.x & 31;
    const float* p = g_Wt + (size_t)row * ND + lane * 8;
    float4 a = *(const float4*)p;
    float4 b = *(const float4*)(p + 4);
    double s = (double)a.x * a.x + (double)a.y * a.y + (double)a.z * a.z + (double)a.w * a.w
             + (double)b.x * b.x + (double)b.y * b.y + (double)b.z * b.z + (double)b.w * b.w;
    #pragma unroll
    for (int off = 16; off > 0; off >>= 1) s += __shfl_down_sync(0xFFFFFFFFu, s, off);
    if (lane == 0) g_wsq[row] = (float)s;
    if (blockIdx.x == 0 && threadIdx.x == 0) { g_accum = 0.0; g_fix_count = 0; g_pair_count = 0; }
}

// ---- prep: X -> fp16 (grid-stride, vectorized) ----
__global__ void __launch_bounds__(256)
convertX_kernel(const float* __restrict__ X) {
    const size_t n4 = (size_t)NV * NN * ND / 4;
    const float4* X4 = (const float4*)X;
    size_t stride = (size_t)gridDim.x * 256;
    for (size_t i = (size_t)blockIdx.x * 256 + threadIdx.x; i < n4; i += stride) {
        float4 x = X4[i];
        __half2* h2 = (__half2*)(&g_Xh[i * 4]);
        h2[0] = __floats2half2_rn(x.x, x.y);
        h2[1] = __floats2half2_rn(x.z, x.w);
    }
}

// ---- main: fp16 HMMA (ldmatrix) + top-3 classification (no fp64 here) ----
// grid (NN/128, NV), 256 thr = 8 warps (4M x 2N), warp tile 32x32, 2 CTAs/SM
__global__ void __launch_bounds__(256, 2)
gemm_argmin_kernel() {
    extern __shared__ char smem[];
    const uint32_t sb = smem_u32(smem);
    const int tid = threadIdx.x, lane = tid & 31, wid = tid >> 5;
    const int wm = wid & 3, wn = wid >> 2;
    const int g = lane >> 2, tg = lane & 3;
    const int v = blockIdx.y, row0 = blockIdx.x * 128;

    {
        float* sw = (float*)(smem + WSQ_S);
        #pragma unroll
        for (int q = 0; q < 4; ++q) sw[tid + q * 256] = g_wsq[v * NK + tid + q * 256];
    }

    const size_t abase = ((size_t)v * NN + row0) * ND;

    // A: all 4 d-tiles resident
    {
        #pragma unroll
        for (int j = 0; j < 16; ++j) {
            int q = tid + j * 256;
            int dc = q >> 10, r = (q >> 3) & 127, c = q & 7;
            cpa16(sb + AOFF + dc * ATILB + r * ROWB + c * 16,
                  (const char*)g_Xh + (abase + (size_t)r * ND + dc * 64 + c * 8) * 2);
        }
        CP_COMMIT();
    }

    auto issueB = [&](int i) {
        int nc = i >> 2, dc = i & 3, buf = i % 3;
        size_t bb = ((size_t)v * NK + nc * 64) * ND + dc * 64;
        #pragma unroll
        for (int j = 0; j < 2; ++j) {
            int q = tid * 2 + j;
            int r = q >> 3, c = q & 7;
            cpa16(sb + BOFF + buf * BTILB + r * ROWB + c * 16,
                  (const char*)g_Wh + (bb + (size_t)r * ND + c * 8) * 2);
        }
        CP_COMMIT();
    };

    float tv[4][3]; int ti[4][3];
    #pragma unroll
    for (int s = 0; s < 4; ++s)
        #pragma unroll
        for (int j = 0; j < 3; ++j) { tv[s][j] = FLT_MAX; ti[s][j] = 0x7FFFFFFF; }

    issueB(0);
    issueB(1);
    const float* sw = (const float*)(smem + WSQ_S);

    const uint32_t aLane = (uint32_t)((wm * 32 + (lane & 15)) * ROWB + ((lane >> 4) << 4));
    const uint32_t bLane = (uint32_t)((wn * 32 + ((lane >> 4) << 3) + (lane & 7)) * ROWB
                                      + (((lane >> 3) & 1) << 4));

    for (int nc = 0; nc < 16; ++nc) {
        float c[2][4][4];
        #pragma unroll
        for (int mf = 0; mf < 2; ++mf)
            #pragma unroll
            for (int nf = 0; nf < 4; ++nf)
                #pragma unroll
                for (int e = 0; e < 4; ++e) c[mf][nf][e] = 0.0f;

        for (int dc = 0; dc < 4; ++dc) {
            int ph = nc * 4 + dc;
            if (ph < 63) { CP_WAIT1(); } else { CP_WAIT0(); }
            __syncthreads();
            if (ph < 62) issueB(ph + 2);

            const uint32_t aB = sb + AOFF + dc * ATILB + aLane;
            const uint32_t bB = sb + BOFF + (ph % 3) * BTILB + bLane;
            #pragma unroll
            for (int ks = 0; ks < 4; ++ks) {
                uint32_t A0[4], A1[4], B0[4], B1[4];
                ldsm4(A0, aB + ks * 32);
                ldsm4(A1, aB + 16 * ROWB + ks * 32);
                ldsm4(B0, bB + ks * 32);
                ldsm4(B1, bB + 16 * ROWB + ks * 32);
                mma16816(c[0][0], A0, B0);     mma16816(c[0][1], A0, B0 + 2);
                mma16816(c[0][2], A0, B1);     mma16816(c[0][3], A0, B1 + 2);
                mma16816(c[1][0], A1, B0);     mma16816(c[1][1], A1, B0 + 2);
                mma16816(c[1][2], A1, B1);     mma16816(c[1][3], A1, B1 + 2);
            }
        }

        #pragma unroll
        for (int mf = 0; mf < 2; ++mf)
            #pragma unroll
            for (int nf = 0; nf < 4; ++nf)
                #pragma unroll
                for (int e = 0; e < 4; ++e) {
                    int col  = nc * 64 + wn * 32 + nf * 8 + tg * 2 + (e & 1);
                    int slot = mf * 2 + (e >> 1);
                    float sc = sw[col] - 2.0f * c[mf][nf][e];
                    float* a = tv[slot]; int* ai = ti[slot];
                    if (sc < a[2]) {
                        if (sc < a[1]) {
                            a[2] = a[1]; ai[2] = ai[1];
                            if (sc < a[0]) { a[1] = a[0]; ai[1] = ai[0]; a[0] = sc; ai[0] = col; }
                            else           { a[1] = sc; ai[1] = col; }
                        } else { a[2] = sc; ai[2] = col; }
                    }
                }
    }

    const unsigned m = 0xFFFFFFFFu;
    #pragma unroll
    for (int off = 1; off < 4; off <<= 1) {
        #pragma unroll
        for (int s = 0; s < 4; ++s) {
            float ov[3]; int oi[3];
            #pragma unroll
            for (int j = 0; j < 3; ++j) {
                ov[j] = __shfl_xor_sync(m, tv[s][j], off);
                oi[j] = __shfl_xor_sync(m, ti[s][j], off);
            }
            #pragma unroll
            for (int j = 0; j < 3; ++j) ins3(ov[j], oi[j], tv[s], ti[s]);
        }
    }

    float* mv = (float*)(smem + MRG);
    int*   mi = (int*)  (smem + MRG + 3072);
    __syncthreads();
    if (tg == 0) {
        #pragma unroll
        for (int s = 0; s < 4; ++s) {
            int rl = wm * 32 + (s >> 1) * 16 + g + (s & 1) * 8;
            #pragma unroll
            for (int j = 0; j < 3; ++j) {
                mv[(wn * 128 + rl) * 3 + j] = tv[s][j];
                mi[(wn * 128 + rl) * 3 + j] = ti[s][j];
            }
        }
    }
    __syncthreads();

    if (tid < 128) {
        float a[3]; int ai[3];
        #pragma unroll
        for (int j = 0; j < 3; ++j) { a[j] = mv[tid * 3 + j]; ai[j] = mi[tid * 3 + j]; }
        #pragma unroll
        for (int j = 0; j < 3; ++j)
            ins3(mv[(128 + tid) * 3 + j], mi[(128 + tid) * 3 + j], a, ai);

        int R = v * NN + row0 + tid;
        g_idx[R] = ai[0];
        float gap2 = a[1] - a[0], gap3 = a[2] - a[0];
        if (gap3 < W1) {
            int slot = atomicAdd(&g_fix_count, 1);
            g_fix_rows[slot] = R;
        } else if (gap2 < W1) {
            int slot = atomicAdd(&g_pair_count, 1);
            g_pair_rows[slot] = R;
            g_pair_cands[slot] = make_int2(ai[0], ai[1]);
        }
    }
}

// ---- exact pair adjudication: one warp per flagged row ----
__global__ void __launch_bounds__(256)
fixpair_kernel(const float* __restrict__ X) {
    int cnt = g_pair_count;
    int nw = gridDim.x * 8;
    int w = blockIdx.x * 8 + (threadIdx.x >> 5);
    int lane = threadIdx.x & 31;
    for (int e = w; e < cnt; e += nw) {
        int R = g_pair_rows[e];
        int2 cd = g_pair_cands[e];
        int v = R >> 13;
        const float* xp = X + (size_t)R * ND + lane * 8;
        double s2[2];
        #pragma unroll
        for (int c = 0; c < 2; ++c) {
            int k = c ? cd.y : cd.x;
            const float* wr = g_Wt + ((size_t)v * NK + k) * ND + lane * 8;
            double dot = 0.0, ws = 0.0;
            #pragma unroll
            for (int j = 0; j < 8; ++j) {
                double wv_ = (double)wr[j];
                dot += (double)xp[j] * wv_;
                ws  += wv_ * wv_;
            }
            double sc = ws - 2.0 * dot;
            #pragma unroll
            for (int off = 16; off > 0; off >>= 1)
                sc += __shfl_down_sync(0xFFFFFFFFu, sc, off);
            s2[c] = sc;
        }
        if (lane == 0) {
            int kk = (s2[1] < s2[0] || (s2[1] == s2[0] && cd.y < cd.x)) ? cd.y : cd.x;
            g_idx[R] = kk;
        }
    }
}

// ---- exact full-row rescore for triple-flagged rows ----
__global__ void __launch_bounds__(256)
fix_kernel(const float* __restrict__ X) {
    __shared__ float xs[ND];
    __shared__ float wv[16];
    __shared__ int   wi[16];
    int cnt = g_fix_count;
    for (int f = blockIdx.x; f < cnt; f += gridDim.x) {
        int R = g_fix_rows[f];
        int v = R >> 13;
        __syncthreads();
        xs[threadIdx.x] = X[(size_t)R * ND + threadIdx.x];
        __syncthreads();

        float b = FLT_MAX, s = FLT_MAX; int bi = 0x7FFFFFFF, si = 0x7FFFFFFF;
        #pragma unroll
        for (int kk = 0; kk < 4; ++kk) {
            int k = threadIdx.x * 4 + kk;
            const float* w = g_Wt + ((size_t)v * NK + k) * ND;
            float dot = 0.0f;
            #pragma unroll 8
            for (int d = 0; d < ND; ++d) dot = fmaf(xs[d], w[d], dot);
            float sc = g_wsq[v * NK + k] - 2.0f * dot;
            if (sc < b || (sc == b && k < bi)) { s = b; si = bi; b = sc; bi = k; }
            else if (sc < s || (sc == s && k < si)) { s = sc; si = k; }
        }
        const unsigned m = 0xFFFFFFFFu;
        #pragma unroll
        for (int off = 1; off < 32; off <<= 1) {
            float ob = __shfl_xor_sync(m, b, off);  int obi = __shfl_xor_sync(m, bi, off);
            float os = __shfl_xor_sync(m, s, off);  int osi = __shfl_xor_sync(m, si, off);
            bool tko = (ob < b) || (ob == b && obi < bi);
            float lb = tko ? b : ob; int lbi = tko ? bi : obi;
            float ws_ = tko ? os : s; int wsi = tko ? osi : si;
            if (tko) { b = ob; bi = obi; }
            if (ws_ < lb || (ws_ == lb && wsi < lbi)) { s = ws_; si = wsi; }
            else                                      { s = lb;  si = lbi; }
        }
        int wrp = threadIdx.x >> 5;
        if ((threadIdx.x & 31) == 0) { wv[wrp * 2] = b; wv[wrp * 2 + 1] = s; wi[wrp * 2] = bi; wi[wrp * 2 + 1] = si; }
        __syncthreads();
        if (threadIdx.x == 0) {
            float B = FLT_MAX, S = FLT_MAX; int Bi = 0x7FFFFFFF, Si = 0x7FFFFFFF;
            for (int q = 0; q < 16; ++q) {
                float vq = wv[q]; int iq = wi[q];
                if (vq < B || (vq == B && iq < Bi)) { S = B; Si = Bi; B = vq; Bi = iq; }
                else if (vq < S || (vq == S && iq < Si)) { S = vq; Si = iq; }
            }
            int kk = Bi;
            if (S - B < MARGIN) {
                const float* Wv_ = g_Wt + (size_t)v * NK * ND;
                double sb2 = dscore_row(xs, Wv_ + (size_t)Bi * ND);
                double ss2 = dscore_row(xs, Wv_ + (size_t)Si * ND);
                if (ss2 < sb2 || (ss2 == sb2 && Si < Bi)) kk = Si;
            }
            g_idx[R] = kk;
        }
        __syncthreads();
    }
}

// ---- gather + loss ----
__global__ void __launch_bounds__(256)
gather_kernel(const float* __restrict__ X, float* __restrict__ out) {
    int R = blockIdx.x * 4 + (threadIdx.x >> 6);
    int lane64 = threadIdx.x & 63;
    int k = g_idx[R];
    int v = R >> 13;
    float4 qv = ((const float4*)(g_Wt + ((size_t)v * NK + k) * ND))[lane64];
    float4 xv = ((const float4*)(X + (size_t)R * ND))[lane64];
    ((float4*)(out + (size_t)R * ND))[lane64] = qv;

    float dx = qv.x - xv.x, dy = qv.y - xv.y, dz = qv.z - xv.z, dw = qv.w - xv.w;
    float s = dx * dx + dy * dy + dz * dz + dw * dw;
    #pragma unroll
    for (int off = 16; off > 0; off >>= 1) s += __shfl_down_sync(0xFFFFFFFFu, s, off);

    __shared__ float ps[8];
    int w = threadIdx.x >> 5, l = threadIdx.x & 31;
    if (l == 0) ps[w] = s;
    __syncthreads();
    if (threadIdx.x == 0) {
        float tot = 0.0f;
        #pragma unroll
        for (int i = 0; i < 8; ++i) tot += ps[i];
        atomicAdd(&g_accum, (double)tot);
    }
}

__global__ void loss_kernel(float* __restrict__ out, long long out_size) {
    const long long VND = (long long)NV * NN * ND;
    double loss = 1.25 * g_accum / (double)VND;
    for (long long i = VND + threadIdx.x; i < out_size; i += blockDim.x)
        out[i] = (float)loss;
}

extern "C" void kernel_launch(void* const* d_in, const int* in_sizes, int n_in,
                              void* d_out, int out_size) {
    const float* X = (const float*)d_in[0];
    const float* E = (const float*)d_in[1];
    float* out = (float*)d_out;

    cudaFuncSetAttribute((const void*)gemm_argmin_kernel,
                         cudaFuncAttributeMaxDynamicSharedMemorySize, SMEM_TOTAL);

    transpose_kernel<<<dim3(NK / 32, ND / 32, NV), dim3(32, 8)>>>(E);
    wsq_kernel<<<2048, 256>>>();
    convertX_kernel<<<2048, 256>>>(X);
    gemm_argmin_kernel<<<dim3(NN / 128, NV), 256, SMEM_TOTAL>>>();
    fixpair_kernel<<<256, 256>>>(X);
    fix_kernel<<<256, 256>>>(X);
    gather_kernel<<<(NV * NN) / 4, 256>>>(X, out);
    loss_kernel<<<1, 32>>>(out, (long long)out_size);
}

// round 14
// speedup vs baseline: 2.5924x; 1.1355x over previous
#include <cuda_runtime.h>
#include <cuda_fp16.h>
#include <cfloat>
#include <cstdint>

#define NV 16
#define NN 8192
#define ND 256
#define NK 1024
#define W1 0.26f          // coarse-score uncertainty window
#define MARGIN 0.05f      // fp32-exact pair-adjudication margin

// ---- smem layout (bytes) ----
#define ROWB   144
#define ATILB  18432
#define BTILB  9216
#define AOFF   0
#define BOFF   73728
#define WSQ_S  101376
#define MRG    105472
#define SMEM_TOTAL 111616

// ---- device scratch ----
__device__ float  g_wsq[NV * NK];
__device__ float  g_Wt[(size_t)NV * NK * ND];                    // [V][K][D] fp32
__device__ __align__(256) __half g_Xh[(size_t)NV * NN * ND];     // X fp16
__device__ __align__(256) __half g_Wh[(size_t)NV * NK * ND];     // Wt fp16
__device__ int    g_idx[NV * NN];
__device__ int    g_fix_count;
__device__ int    g_pair_count;
__device__ int    g_fix_rows[NV * NN];
__device__ int    g_pair_rows[NV * NN];
__device__ int2   g_pair_cands[NV * NN];
__device__ double g_accum;

// ---- helpers ----
__device__ __forceinline__ uint32_t smem_u32(const void* p) {
    uint32_t a;
    asm("{ .reg .u64 t; cvta.to.shared.u64 t, %1; cvt.u32.u64 %0, t; }" : "=r"(a) : "l"(p));
    return a;
}
__device__ __forceinline__ void cpa16(uint32_t dst, const void* src) {
    asm volatile("cp.async.cg.shared.global [%0], [%1], 16;" :: "r"(dst), "l"(src));
}
#define CP_COMMIT() asm volatile("cp.async.commit_group;" ::: "memory")
#define CP_WAIT1()  asm volatile("cp.async.wait_group 1;" ::: "memory")
#define CP_WAIT0()  asm volatile("cp.async.wait_group 0;" ::: "memory")
__device__ __forceinline__ void ldsm4(uint32_t* r, uint32_t a) {
    asm volatile("ldmatrix.sync.aligned.m8n8.x4.shared.b16 {%0,%1,%2,%3}, [%4];"
        : "=r"(r[0]), "=r"(r[1]), "=r"(r[2]), "=r"(r[3]) : "r"(a));
}
__device__ __forceinline__ void mma16816(float* c, const uint32_t* a, const uint32_t* b) {
    asm volatile("mma.sync.aligned.m16n8k16.row.col.f32.f16.f16.f32 "
        "{%0,%1,%2,%3}, {%4,%5,%6,%7}, {%8,%9}, {%0,%1,%2,%3};"
        : "+f"(c[0]), "+f"(c[1]), "+f"(c[2]), "+f"(c[3])
        : "r"(a[0]), "r"(a[1]), "r"(a[2]), "r"(a[3]), "r"(b[0]), "r"(b[1]));
}
__device__ __forceinline__ void ins3(float v, int i, float* a, int* ai) {
    if (v < a[0] || (v == a[0] && i < ai[0])) {
        a[2] = a[1]; ai[2] = ai[1]; a[1] = a[0]; ai[1] = ai[0]; a[0] = v; ai[0] = i;
    } else if (v < a[1] || (v == a[1] && i < ai[1])) {
        a[2] = a[1]; ai[2] = ai[1]; a[1] = v; ai[1] = i;
    } else if (v < a[2] || (v == a[2] && i < ai[2])) {
        a[2] = v; ai[2] = i;
    }
}

// warp-parallel exact fp64 score (xrow may be smem or gmem; wrow contiguous)
__device__ double wscore64(const float* __restrict__ xrow, const float* __restrict__ wrow, int lane) {
    double dot = 0.0, ws = 0.0;
    #pragma unroll
    for (int j = lane; j < ND; j += 32) {
        double w = (double)wrow[j];
        dot += (double)xrow[j] * w;
        ws  += w * w;
    }
    double sc = ws - 2.0 * dot;
    #pragma unroll
    for (int off = 16; off > 0; off >>= 1)
        sc += __shfl_down_sync(0xFFFFFFFFu, sc, off);
    return __shfl_sync(0xFFFFFFFFu, sc, 0);
}

// ---- prep: transpose E -> g_Wt fp32 + g_Wh fp16 (fused) ----
__global__ void transpose_kernel(const float* __restrict__ E) {
    __shared__ float t[32][33];
    int v = blockIdx.z, k0 = blockIdx.x * 32, d0 = blockIdx.y * 32;
    int tx = threadIdx.x, ty = threadIdx.y;
    const float* Ev = E + (size_t)v * ND * NK;
    #pragma unroll
    for (int j = 0; j < 32; j += 8) t[ty + j][tx] = Ev[(size_t)(d0 + ty + j) * NK + k0 + tx];
    __syncthreads();
    float* Wv = g_Wt + (size_t)v * NK * ND;
    __half* Hv = g_Wh + (size_t)v * NK * ND;
    #pragma unroll
    for (int j = 0; j < 32; j += 8) {
        float val = t[tx][ty + j];
        size_t o = (size_t)(k0 + ty + j) * ND + d0 + tx;
        Wv[o] = val;
        Hv[o] = __float2half_rn(val);
    }
}

// ---- prep: ||w||^2 from transposed Wt ----
__global__ void wsq_kernel() {
    int row = blockIdx.x * 8 + (threadIdx.x >> 5);
    int lane = threadIdx.x & 31;
    const float* p = g_Wt + (size_t)row * ND + lane * 8;
    float4 a = *(const float4*)p;
    float4 b = *(const float4*)(p + 4);
    double s = (double)a.x * a.x + (double)a.y * a.y + (double)a.z * a.z + (double)a.w * a.w
             + (double)b.x * b.x + (double)b.y * b.y + (double)b.z * b.z + (double)b.w * b.w;
    #pragma unroll
    for (int off = 16; off > 0; off >>= 1) s += __shfl_down_sync(0xFFFFFFFFu, s, off);
    if (lane == 0) g_wsq[row] = (float)s;
    if (blockIdx.x == 0 && threadIdx.x == 0) { g_accum = 0.0; g_fix_count = 0; g_pair_count = 0; }
}

// ---- prep: X -> fp16 ----
__global__ void __launch_bounds__(256)
convertX_kernel(const float* __restrict__ X) {
    const size_t n4 = (size_t)NV * NN * ND / 4;
    const float4* X4 = (const float4*)X;
    size_t stride = (size_t)gridDim.x * 256;
    for (size_t i = (size_t)blockIdx.x * 256 + threadIdx.x; i < n4; i += stride) {
        float4 x = X4[i];
        __half2* h2 = (__half2*)(&g_Xh[i * 4]);
        h2[0] = __floats2half2_rn(x.x, x.y);
        h2[1] = __floats2half2_rn(x.z, x.w);
    }
}

// ---- main: fp16 HMMA + top-3 classification + fused gather/loss ----
// grid (NN/128, NV), 256 thr = 8 warps (4M x 2N), warp tile 32x32, 2 CTAs/SM
__global__ void __launch_bounds__(256, 2)
gemm_argmin_kernel(const float* __restrict__ X, float* __restrict__ out) {
    extern __shared__ char smem[];
    const uint32_t sb = smem_u32(smem);
    const int tid = threadIdx.x, lane = tid & 31, wid = tid >> 5;
    const int wm = wid & 3, wn = wid >> 2;
    const int g = lane >> 2, tg = lane & 3;
    const int v = blockIdx.y, row0 = blockIdx.x * 128;

    {
        float* sw = (float*)(smem + WSQ_S);
        #pragma unroll
        for (int q = 0; q < 4; ++q) sw[tid + q * 256] = g_wsq[v * NK + tid + q * 256];
    }

    const size_t abase = ((size_t)v * NN + row0) * ND;

    // A: all 4 d-tiles resident
    {
        #pragma unroll
        for (int j = 0; j < 16; ++j) {
            int q = tid + j * 256;
            int dc = q >> 10, r = (q >> 3) & 127, c = q & 7;
            cpa16(sb + AOFF + dc * ATILB + r * ROWB + c * 16,
                  (const char*)g_Xh + (abase + (size_t)r * ND + dc * 64 + c * 8) * 2);
        }
        CP_COMMIT();
    }

    auto issueB = [&](int i) {
        int nc = i >> 2, dc = i & 3, buf = i % 3;
        size_t bb = ((size_t)v * NK + nc * 64) * ND + dc * 64;
        #pragma unroll
        for (int j = 0; j < 2; ++j) {
            int q = tid * 2 + j;
            int r = q >> 3, c = q & 7;
            cpa16(sb + BOFF + buf * BTILB + r * ROWB + c * 16,
                  (const char*)g_Wh + (bb + (size_t)r * ND + c * 8) * 2);
        }
        CP_COMMIT();
    };

    float tv[4][3]; int ti[4][3];
    #pragma unroll
    for (int s = 0; s < 4; ++s)
        #pragma unroll
        for (int j = 0; j < 3; ++j) { tv[s][j] = FLT_MAX; ti[s][j] = 0x7FFFFFFF; }

    issueB(0);
    issueB(1);
    const float* sw = (const float*)(smem + WSQ_S);

    const uint32_t aLane = (uint32_t)((wm * 32 + (lane & 15)) * ROWB + ((lane >> 4) << 4));
    const uint32_t bLane = (uint32_t)((wn * 32 + ((lane >> 4) << 3) + (lane & 7)) * ROWB
                                      + (((lane >> 3) & 1) << 4));

    for (int nc = 0; nc < 16; ++nc) {
        float c[2][4][4];
        #pragma unroll
        for (int mf = 0; mf < 2; ++mf)
            #pragma unroll
            for (int nf = 0; nf < 4; ++nf)
                #pragma unroll
                for (int e = 0; e < 4; ++e) c[mf][nf][e] = 0.0f;

        for (int dc = 0; dc < 4; ++dc) {
            int ph = nc * 4 + dc;
            if (ph < 63) { CP_WAIT1(); } else { CP_WAIT0(); }
            __syncthreads();
            if (ph < 62) issueB(ph + 2);

            const uint32_t aB = sb + AOFF + dc * ATILB + aLane;
            const uint32_t bB = sb + BOFF + (ph % 3) * BTILB + bLane;
            #pragma unroll
            for (int ks = 0; ks < 4; ++ks) {
                uint32_t A0[4], A1[4], B0[4], B1[4];
                ldsm4(A0, aB + ks * 32);
                ldsm4(A1, aB + 16 * ROWB + ks * 32);
                ldsm4(B0, bB + ks * 32);
                ldsm4(B1, bB + 16 * ROWB + ks * 32);
                mma16816(c[0][0], A0, B0);     mma16816(c[0][1], A0, B0 + 2);
                mma16816(c[0][2], A0, B1);     mma16816(c[0][3], A0, B1 + 2);
                mma16816(c[1][0], A1, B0);     mma16816(c[1][1], A1, B0 + 2);
                mma16816(c[1][2], A1, B1);     mma16816(c[1][3], A1, B1 + 2);
            }
        }

        #pragma unroll
        for (int mf = 0; mf < 2; ++mf)
            #pragma unroll
            for (int nf = 0; nf < 4; ++nf)
                #pragma unroll
                for (int e = 0; e < 4; ++e) {
                    int col  = nc * 64 + wn * 32 + nf * 8 + tg * 2 + (e & 1);
                    int slot = mf * 2 + (e >> 1);
                    float sc = sw[col] - 2.0f * c[mf][nf][e];
                    float* a = tv[slot]; int* ai = ti[slot];
                    if (sc < a[2]) {
                        if (sc < a[1]) {
                            a[2] = a[1]; ai[2] = ai[1];
                            if (sc < a[0]) { a[1] = a[0]; ai[1] = ai[0]; a[0] = sc; ai[0] = col; }
                            else           { a[1] = sc; ai[1] = col; }
                        } else { a[2] = sc; ai[2] = col; }
                    }
                }
    }

    const unsigned m = 0xFFFFFFFFu;
    #pragma unroll
    for (int off = 1; off < 4; off <<= 1) {
        #pragma unroll
        for (int s = 0; s < 4; ++s) {
            float ov[3]; int oi[3];
            #pragma unroll
            for (int j = 0; j < 3; ++j) {
                ov[j] = __shfl_xor_sync(m, tv[s][j], off);
                oi[j] = __shfl_xor_sync(m, ti[s][j], off);
            }
            #pragma unroll
            for (int j = 0; j < 3; ++j) ins3(ov[j], oi[j], tv[s], ti[s]);
        }
    }

    float* mv = (float*)(smem + MRG);
    int*   mi = (int*)  (smem + MRG + 3072);
    __syncthreads();
    if (tg == 0) {
        #pragma unroll
        for (int s = 0; s < 4; ++s) {
            int rl = wm * 32 + (s >> 1) * 16 + g + (s & 1) * 8;
            #pragma unroll
            for (int j = 0; j < 3; ++j) {
                mv[(wn * 128 + rl) * 3 + j] = tv[s][j];
                mi[(wn * 128 + rl) * 3 + j] = ti[s][j];
            }
        }
    }
    __syncthreads();

    int provisional = 0;
    if (tid < 128) {
        float a[3]; int ai[3];
        #pragma unroll
        for (int j = 0; j < 3; ++j) { a[j] = mv[tid * 3 + j]; ai[j] = mi[tid * 3 + j]; }
        #pragma unroll
        for (int j = 0; j < 3; ++j)
            ins3(mv[(128 + tid) * 3 + j], mi[(128 + tid) * 3 + j], a, ai);

        int R = v * NN + row0 + tid;
        provisional = ai[0];
        g_idx[R] = ai[0];
        float gap2 = a[1] - a[0], gap3 = a[2] - a[0];
        if (gap3 < W1) {
            int slot = atomicAdd(&g_fix_count, 1);
            g_fix_rows[slot] = R;
        } else if (gap2 < W1) {
            int slot = atomicAdd(&g_pair_count, 1);
            g_pair_rows[slot] = R;
            g_pair_cands[slot] = make_int2(ai[0], ai[1]);
        }
    }

    // ---- fused gather + loss (provisional; fix kernels correct the ~2% flips) ----
    __syncthreads();                         // mv/mi reads done; reuse MRG
    int*   sk    = (int*)(smem + MRG);       // [128] chosen k per row
    float* wsums = (float*)(smem + MRG + 512);
    if (tid < 128) sk[tid] = provisional;
    __syncthreads();

    float part = 0.0f;
    const float* Xv = X + ((size_t)v * NN + row0) * ND;
    float* Ov = out + ((size_t)v * NN + row0) * ND;
    for (int r = wid * 16; r < wid * 16 + 16; ++r) {
        int k = sk[r];
        const float4* wrow = (const float4*)(g_Wt + ((size_t)v * NK + k) * ND);
        const float4* xrow = (const float4*)(Xv + (size_t)r * ND);
        float4* orow = (float4*)(Ov + (size_t)r * ND);
        #pragma unroll
        for (int j = 0; j < 2; ++j) {
            float4 qv = wrow[lane + j * 32];
            float4 xv = xrow[lane + j * 32];
            orow[lane + j * 32] = qv;
            float dx = qv.x - xv.x, dy = qv.y - xv.y, dz = qv.z - xv.z, dw = qv.w - xv.w;
            part += dx * dx + dy * dy + dz * dz + dw * dw;
        }
    }
    #pragma unroll
    for (int off = 16; off > 0; off >>= 1) part += __shfl_down_sync(m, part, off);
    if (lane == 0) wsums[wid] = part;
    __syncthreads();
    if (tid == 0) {
        double t = 0.0;
        #pragma unroll
        for (int i = 0; i < 8; ++i) t += (double)wsums[i];
        atomicAdd(&g_accum, t);
    }
}

// ---- exact pair adjudication + output/loss correction: one warp per flagged row ----
__global__ void __launch_bounds__(256)
fixpair_kernel(const float* __restrict__ X, float* __restrict__ out) {
    int cnt = g_pair_count;
    int nw = gridDim.x * 8;
    int w = blockIdx.x * 8 + (threadIdx.x >> 5);
    int lane = threadIdx.x & 31;
    for (int e = w; e < cnt; e += nw) {
        int R = g_pair_rows[e];
        int2 cd = g_pair_cands[e];
        int v = R >> 13;
        const float* xrow = X + (size_t)R * ND;
        const float* Wv = g_Wt + (size_t)v * NK * ND;
        double s0 = wscore64(xrow, Wv + (size_t)cd.x * ND, lane);
        double s1 = wscore64(xrow, Wv + (size_t)cd.y * ND, lane);
        bool flip = (s1 < s0) || (s1 == s0 && cd.y < cd.x);
        if (flip) {
            const float4* wr = (const float4*)(Wv + (size_t)cd.y * ND);
            float4* orow = (float4*)(out + (size_t)R * ND);
            orow[lane] = wr[lane];
            orow[lane + 32] = wr[lane + 32];
            if (lane == 0) {
                g_idx[R] = cd.y;
                atomicAdd(&g_accum, s1 - s0);   // delta(sse) == delta(score)
            }
        }
    }
}

// ---- exact full-row rescore + correction for triple-flagged rows ----
__global__ void __launch_bounds__(256)
fix_kernel(const float* __restrict__ X, float* __restrict__ out) {
    __shared__ float xs[ND];
    __shared__ float wv[16];
    __shared__ int   wi[16];
    __shared__ int   s_kk, s_old;
    __shared__ double s_delta;
    int cnt = g_fix_count;
    for (int f = blockIdx.x; f < cnt; f += gridDim.x) {
        int R = g_fix_rows[f];
        int v = R >> 13;
        __syncthreads();
        xs[threadIdx.x] = X[(size_t)R * ND + threadIdx.x];
        __syncthreads();

        float b = FLT_MAX, s = FLT_MAX; int bi = 0x7FFFFFFF, si = 0x7FFFFFFF;
        #pragma unroll
        for (int kk = 0; kk < 4; ++kk) {
            int k = threadIdx.x * 4 + kk;
            const float* w = g_Wt + ((size_t)v * NK + k) * ND;
            float dot = 0.0f;
            #pragma unroll 8
            for (int d = 0; d < ND; ++d) dot = fmaf(xs[d], w[d], dot);
            float sc = g_wsq[v * NK + k] - 2.0f * dot;
            if (sc < b || (sc == b && k < bi)) { s = b; si = bi; b = sc; bi = k; }
            else if (sc < s || (sc == s && k < si)) { s = sc; si = k; }
        }
        const unsigned m = 0xFFFFFFFFu;
        #pragma unroll
        for (int off = 1; off < 32; off <<= 1) {
            float ob = __shfl_xor_sync(m, b, off);  int obi = __shfl_xor_sync(m, bi, off);
            float os = __shfl_xor_sync(m, s, off);  int osi = __shfl_xor_sync(m, si, off);
            bool tko = (ob < b) || (ob == b && obi < bi);
            float lb = tko ? b : ob; int lbi = tko ? bi : obi;
            float ws_ = tko ? os : s; int wsi = tko ? osi : si;
            if (tko) { b = ob; bi = obi; }
            if (ws_ < lb || (ws_ == lb && wsi < lbi)) { s = ws_; si = wsi; }
            else                                      { s = lb;  si = lbi; }
        }
        int wrp = threadIdx.x >> 5;
        if ((threadIdx.x & 31) == 0) { wv[wrp * 2] = b; wv[wrp * 2 + 1] = s; wi[wrp * 2] = bi; wi[wrp * 2 + 1] = si; }
        __syncthreads();
        if (threadIdx.x == 0) {
            float B = FLT_MAX, S = FLT_MAX; int Bi = 0x7FFFFFFF, Si = 0x7FFFFFFF;
            for (int q = 0; q < 16; ++q) {
                float vq = wv[q]; int iq = wi[q];
                if (vq < B || (vq == B && iq < Bi)) { S = B; Si = Bi; B = vq; Bi = iq; }
                else if (vq < S || (vq == S && iq < Si)) { S = vq; Si = iq; }
            }
            wv[0] = S - B; wi[0] = Bi; wi[1] = Si;
        }
        __syncthreads();
        // warp 0: fp64 adjudication + delta
        if (threadIdx.x < 32) {
            int lane = threadIdx.x;
            int Bi = wi[0], Si = wi[1];
            const float* Wv = g_Wt + (size_t)v * NK * ND;
            int kk = Bi;
            if (wv[0] < MARGIN) {
                double sb2 = wscore64(xs, Wv + (size_t)Bi * ND, lane);
                double ss2 = wscore64(xs, Wv + (size_t)Si * ND, lane);
                if (ss2 < sb2 || (ss2 == sb2 && Si < Bi)) kk = Si;
            }
            int old = g_idx[R];
            double delta = 0.0;
            if (kk != old) {
                double sn = wscore64(xs, Wv + (size_t)kk * ND, lane);
                double so = wscore64(xs, Wv + (size_t)old * ND, lane);
                delta = sn - so;
            }
            if (lane == 0) { s_kk = kk; s_old = old; s_delta = delta; }
        }
        __syncthreads();
        if (s_kk != s_old) {
            out[(size_t)R * ND + threadIdx.x] = g_Wt[((size_t)v * NK + s_kk) * ND + threadIdx.x];
            if (threadIdx.x == 0) {
                g_idx[R] = s_kk;
                atomicAdd(&g_accum, s_delta);
            }
        }
        __syncthreads();
    }
}

// ---- loss writeback ----
__global__ void loss_kernel(float* __restrict__ out, long long out_size) {
    const long long VND = (long long)NV * NN * ND;
    double loss = 1.25 * g_accum / (double)VND;
    for (long long i = VND + threadIdx.x; i < out_size; i += blockDim.x)
        out[i] = (float)loss;
}

extern "C" void kernel_launch(void* const* d_in, const int* in_sizes, int n_in,
                              void* d_out, int out_size) {
    const float* X = (const float*)d_in[0];
    const float* E = (const float*)d_in[1];
    float* out = (float*)d_out;

    cudaFuncSetAttribute((const void*)gemm_argmin_kernel,
                         cudaFuncAttributeMaxDynamicSharedMemorySize, SMEM_TOTAL);

    transpose_kernel<<<dim3(NK / 32, ND / 32, NV), dim3(32, 8)>>>(E);
    wsq_kernel<<<2048, 256>>>();
    convertX_kernel<<<2048, 256>>>(X);
    gemm_argmin_kernel<<<dim3(NN / 128, NV), 256, SMEM_TOTAL>>>(X, out);
    fixpair_kernel<<<256, 256>>>(X, out);
    fix_kernel<<<256, 256>>>(X, out);
    loss_kernel<<<1, 32>>>(out, (long long)out_size);
}

// round 15
// speedup vs baseline: 2.6945x; 1.0394x over previous
#include <cuda_runtime.h>
#include <cuda_fp16.h>
#include <cfloat>
#include <cstdint>

#define NV 16
#define NN 8192
#define ND 256
#define NK 1024
#define W1 0.26f          // coarse-score uncertainty window
#define MARGIN 0.05f      // fp32-exact pair-adjudication margin

// ---- smem layout (bytes) ----
#define ROWB   144
#define ATILB  18432
#define BTILB  9216
#define AOFF   0
#define BOFF   73728
#define WSQ_S  101376
#define MRG    105472
#define SMEM_TOTAL 111616

// ---- device scratch ----
__device__ float  g_wsq[NV * NK];
__device__ float  g_Wt[(size_t)NV * NK * ND];                    // [V][K][D] fp32
__device__ __align__(256) __half g_Wh[(size_t)NV * NK * ND];     // Wt fp16
__device__ int    g_idx[NV * NN];
__device__ int    g_fix_count;
__device__ int    g_pair_count;
__device__ int    g_fix_rows[NV * NN];
__device__ int    g_pair_rows[NV * NN];
__device__ int2   g_pair_cands[NV * NN];
__device__ double g_accum;

// ---- helpers ----
__device__ __forceinline__ uint32_t smem_u32(const void* p) {
    uint32_t a;
    asm("{ .reg .u64 t; cvta.to.shared.u64 t, %1; cvt.u32.u64 %0, t; }" : "=r"(a) : "l"(p));
    return a;
}
__device__ __forceinline__ void cpa16(uint32_t dst, const void* src) {
    asm volatile("cp.async.cg.shared.global [%0], [%1], 16;" :: "r"(dst), "l"(src));
}
#define CP_COMMIT() asm volatile("cp.async.commit_group;" ::: "memory")
#define CP_WAIT1()  asm volatile("cp.async.wait_group 1;" ::: "memory")
#define CP_WAIT0()  asm volatile("cp.async.wait_group 0;" ::: "memory")
__device__ __forceinline__ void ldsm4(uint32_t* r, uint32_t a) {
    asm volatile("ldmatrix.sync.aligned.m8n8.x4.shared.b16 {%0,%1,%2,%3}, [%4];"
        : "=r"(r[0]), "=r"(r[1]), "=r"(r[2]), "=r"(r[3]) : "r"(a));
}
__device__ __forceinline__ void mma16816(float* c, const uint32_t* a, const uint32_t* b) {
    asm volatile("mma.sync.aligned.m16n8k16.row.col.f32.f16.f16.f32 "
        "{%0,%1,%2,%3}, {%4,%5,%6,%7}, {%8,%9}, {%0,%1,%2,%3};"
        : "+f"(c[0]), "+f"(c[1]), "+f"(c[2]), "+f"(c[3])
        : "r"(a[0]), "r"(a[1]), "r"(a[2]), "r"(a[3]), "r"(b[0]), "r"(b[1]));
}
__device__ __forceinline__ void ins3(float v, int i, float* a, int* ai) {
    if (v < a[0] || (v == a[0] && i < ai[0])) {
        a[2] = a[1]; ai[2] = ai[1]; a[1] = a[0]; ai[1] = ai[0]; a[0] = v; ai[0] = i;
    } else if (v < a[1] || (v == a[1] && i < ai[1])) {
        a[2] = a[1]; ai[2] = ai[1]; a[1] = v; ai[1] = i;
    } else if (v < a[2] || (v == a[2] && i < ai[2])) {
        a[2] = v; ai[2] = i;
    }
}

// warp-parallel exact fp64 score (wrow contiguous)
__device__ double wscore64(const float* __restrict__ xrow, const float* __restrict__ wrow, int lane) {
    double dot = 0.0, ws = 0.0;
    #pragma unroll
    for (int j = lane; j < ND; j += 32) {
        double w = (double)wrow[j];
        dot += (double)xrow[j] * w;
        ws  += w * w;
    }
    double sc = ws - 2.0 * dot;
    #pragma unroll
    for (int off = 16; off > 0; off >>= 1)
        sc += __shfl_down_sync(0xFFFFFFFFu, sc, off);
    return __shfl_sync(0xFFFFFFFFu, sc, 0);
}

// ---- prep: transpose E -> g_Wt fp32 + g_Wh fp16 (fused) ----
__global__ void transpose_kernel(const float* __restrict__ E) {
    __shared__ float t[32][33];
    int v = blockIdx.z, k0 = blockIdx.x * 32, d0 = blockIdx.y * 32;
    int tx = threadIdx.x, ty = threadIdx.y;
    const float* Ev = E + (size_t)v * ND * NK;
    #pragma unroll
    for (int j = 0; j < 32; j += 8) t[ty + j][tx] = Ev[(size_t)(d0 + ty + j) * NK + k0 + tx];
    __syncthreads();
    float* Wv = g_Wt + (size_t)v * NK * ND;
    __half* Hv = g_Wh + (size_t)v * NK * ND;
    #pragma unroll
    for (int j = 0; j < 32; j += 8) {
        float val = t[tx][ty + j];
        size_t o = (size_t)(k0 + ty + j) * ND + d0 + tx;
        Wv[o] = val;
        Hv[o] = __float2half_rn(val);
    }
}

// ---- prep: ||w||^2 from transposed Wt ----
__global__ void wsq_kernel() {
    int row = blockIdx.x * 8 + (threadIdx.x >> 5);
    int lane = threadIdx.x & 31;
    const float* p = g_Wt + (size_t)row * ND + lane * 8;
    float4 a = *(const float4*)p;
    float4 b = *(const float4*)(p + 4);
    double s = (double)a.x * a.x + (double)a.y * a.y + (double)a.z * a.z + (double)a.w * a.w
             + (double)b.x * b.x + (double)b.y * b.y + (double)b.z * b.z + (double)b.w * b.w;
    #pragma unroll
    for (int off = 16; off > 0; off >>= 1) s += __shfl_down_sync(0xFFFFFFFFu, s, off);
    if (lane == 0) g_wsq[row] = (float)s;
    if (blockIdx.x == 0 && threadIdx.x == 0) { g_accum = 0.0; g_fix_count = 0; g_pair_count = 0; }
}

// ---- main: fp16 HMMA + top-3 classification + fused gather/loss + fused X conversion ----
// grid (NN/128, NV), 256 thr = 8 warps (4M x 2N), warp tile 32x32, 2 CTAs/SM
__global__ void __launch_bounds__(256, 2)
gemm_argmin_kernel(const float* __restrict__ X, float* __restrict__ out) {
    extern __shared__ char smem[];
    const uint32_t sb = smem_u32(smem);
    const int tid = threadIdx.x, lane = tid & 31, wid = tid >> 5;
    const int wm = wid & 3, wn = wid >> 2;
    const int g = lane >> 2, tg = lane & 3;
    const int v = blockIdx.y, row0 = blockIdx.x * 128;

    {
        float* sw = (float*)(smem + WSQ_S);
        #pragma unroll
        for (int q = 0; q < 4; ++q) sw[tid + q * 256] = g_wsq[v * NK + tid + q * 256];
    }

    auto issueB = [&](int i) {
        int nc = i >> 2, dc = i & 3, buf = i % 3;
        size_t bb = ((size_t)v * NK + nc * 64) * ND + dc * 64;
        #pragma unroll
        for (int j = 0; j < 2; ++j) {
            int q = tid * 2 + j;
            int r = q >> 3, c = q & 7;
            cpa16(sb + BOFF + buf * BTILB + r * ROWB + c * 16,
                  (const char*)g_Wh + (bb + (size_t)r * ND + c * 8) * 2);
        }
        CP_COMMIT();
    };

    issueB(0);
    issueB(1);

    // A: load fp32 X, convert to fp16, store into resident padded tiles
    // (LDG latency overlaps the B cp.async chain above)
    const size_t abase = ((size_t)v * NN + row0) * ND;
    {
        #pragma unroll
        for (int j = 0; j < 32; ++j) {
            int q = tid + j * 256;              // 0..8191 float4 units
            int r = q >> 6;
            int dc = (q >> 4) & 3;
            int c = q & 15;
            float4 x = *(const float4*)(X + abase + (size_t)r * ND + dc * 64 + c * 4);
            __half2 h0 = __floats2half2_rn(x.x, x.y);
            __half2 h1 = __floats2half2_rn(x.z, x.w);
            char* dst = smem + AOFF + dc * ATILB + r * ROWB + c * 8;
            *(__half2*)(dst)     = h0;
            *(__half2*)(dst + 4) = h1;
        }
    }

    float tv[4][3]; int ti[4][3];
    #pragma unroll
    for (int s = 0; s < 4; ++s)
        #pragma unroll
        for (int j = 0; j < 3; ++j) { tv[s][j] = FLT_MAX; ti[s][j] = 0x7FFFFFFF; }

    const float* sw = (const float*)(smem + WSQ_S);

    const uint32_t aLane = (uint32_t)((wm * 32 + (lane & 15)) * ROWB + ((lane >> 4) << 4));
    const uint32_t bLane = (uint32_t)((wn * 32 + ((lane >> 4) << 3) + (lane & 7)) * ROWB
                                      + (((lane >> 3) & 1) << 4));

    for (int nc = 0; nc < 16; ++nc) {
        float c[2][4][4];
        #pragma unroll
        for (int mf = 0; mf < 2; ++mf)
            #pragma unroll
            for (int nf = 0; nf < 4; ++nf)
                #pragma unroll
                for (int e = 0; e < 4; ++e) c[mf][nf][e] = 0.0f;

        for (int dc = 0; dc < 4; ++dc) {
            int ph = nc * 4 + dc;
            if (ph < 63) { CP_WAIT1(); } else { CP_WAIT0(); }
            __syncthreads();
            if (ph < 62) issueB(ph + 2);

            const uint32_t aB = sb + AOFF + dc * ATILB + aLane;
            const uint32_t bB = sb + BOFF + (ph % 3) * BTILB + bLane;
            #pragma unroll
            for (int ks = 0; ks < 4; ++ks) {
                uint32_t A0[4], A1[4], B0[4], B1[4];
                ldsm4(A0, aB + ks * 32);
                ldsm4(A1, aB + 16 * ROWB + ks * 32);
                ldsm4(B0, bB + ks * 32);
                ldsm4(B1, bB + 16 * ROWB + ks * 32);
                mma16816(c[0][0], A0, B0);     mma16816(c[0][1], A0, B0 + 2);
                mma16816(c[0][2], A0, B1);     mma16816(c[0][3], A0, B1 + 2);
                mma16816(c[1][0], A1, B0);     mma16816(c[1][1], A1, B0 + 2);
                mma16816(c[1][2], A1, B1);     mma16816(c[1][3], A1, B1 + 2);
            }
        }

        #pragma unroll
        for (int mf = 0; mf < 2; ++mf)
            #pragma unroll
            for (int nf = 0; nf < 4; ++nf)
                #pragma unroll
                for (int e = 0; e < 4; ++e) {
                    int col  = nc * 64 + wn * 32 + nf * 8 + tg * 2 + (e & 1);
                    int slot = mf * 2 + (e >> 1);
                    float sc = sw[col] - 2.0f * c[mf][nf][e];
                    float* a = tv[slot]; int* ai = ti[slot];
                    if (sc < a[2]) {
                        if (sc < a[1]) {
                            a[2] = a[1]; ai[2] = ai[1];
                            if (sc < a[0]) { a[1] = a[0]; ai[1] = ai[0]; a[0] = sc; ai[0] = col; }
                            else           { a[1] = sc; ai[1] = col; }
                        } else { a[2] = sc; ai[2] = col; }
                    }
                }
    }

    const unsigned m = 0xFFFFFFFFu;
    #pragma unroll
    for (int off = 1; off < 4; off <<= 1) {
        #pragma unroll
        for (int s = 0; s < 4; ++s) {
            float ov[3]; int oi[3];
            #pragma unroll
            for (int j = 0; j < 3; ++j) {
                ov[j] = __shfl_xor_sync(m, tv[s][j], off);
                oi[j] = __shfl_xor_sync(m, ti[s][j], off);
            }
            #pragma unroll
            for (int j = 0; j < 3; ++j) ins3(ov[j], oi[j], tv[s], ti[s]);
        }
    }

    float* mv = (float*)(smem + MRG);
    int*   mi = (int*)  (smem + MRG + 3072);
    __syncthreads();
    if (tg == 0) {
        #pragma unroll
        for (int s = 0; s < 4; ++s) {
            int rl = wm * 32 + (s >> 1) * 16 + g + (s & 1) * 8;
            #pragma unroll
            for (int j = 0; j < 3; ++j) {
                mv[(wn * 128 + rl) * 3 + j] = tv[s][j];
                mi[(wn * 128 + rl) * 3 + j] = ti[s][j];
            }
        }
    }
    __syncthreads();

    int provisional = 0;
    if (tid < 128) {
        float a[3]; int ai[3];
        #pragma unroll
        for (int j = 0; j < 3; ++j) { a[j] = mv[tid * 3 + j]; ai[j] = mi[tid * 3 + j]; }
        #pragma unroll
        for (int j = 0; j < 3; ++j)
            ins3(mv[(128 + tid) * 3 + j], mi[(128 + tid) * 3 + j], a, ai);

        int R = v * NN + row0 + tid;
        provisional = ai[0];
        g_idx[R] = ai[0];
        float gap2 = a[1] - a[0], gap3 = a[2] - a[0];
        if (gap3 < W1) {
            int slot = atomicAdd(&g_fix_count, 1);
            g_fix_rows[slot] = R;
        } else if (gap2 < W1) {
            int slot = atomicAdd(&g_pair_count, 1);
            g_pair_rows[slot] = R;
            g_pair_cands[slot] = make_int2(ai[0], ai[1]);
        }
    }

    // ---- fused gather + loss (provisional; fix kernels correct the ~2% flips) ----
    __syncthreads();
    int*   sk    = (int*)(smem + MRG);
    float* wsums = (float*)(smem + MRG + 512);
    if (tid < 128) sk[tid] = provisional;
    __syncthreads();

    float part = 0.0f;
    const float* Xv = X + ((size_t)v * NN + row0) * ND;
    float* Ov = out + ((size_t)v * NN + row0) * ND;
    for (int r = wid * 16; r < wid * 16 + 16; ++r) {
        int k = sk[r];
        const float4* wrow = (const float4*)(g_Wt + ((size_t)v * NK + k) * ND);
        const float4* xrow = (const float4*)(Xv + (size_t)r * ND);
        float4* orow = (float4*)(Ov + (size_t)r * ND);
        #pragma unroll
        for (int j = 0; j < 2; ++j) {
            float4 qv = wrow[lane + j * 32];
            float4 xv = xrow[lane + j * 32];
            orow[lane + j * 32] = qv;
            float dx = qv.x - xv.x, dy = qv.y - xv.y, dz = qv.z - xv.z, dw = qv.w - xv.w;
            part += dx * dx + dy * dy + dz * dz + dw * dw;
        }
    }
    #pragma unroll
    for (int off = 16; off > 0; off >>= 1) part += __shfl_down_sync(m, part, off);
    if (lane == 0) wsums[wid] = part;
    __syncthreads();
    if (tid == 0) {
        double t = 0.0;
        #pragma unroll
        for (int i = 0; i < 8; ++i) t += (double)wsums[i];
        atomicAdd(&g_accum, t);
    }
}

// ---- exact pair adjudication + output/loss correction: one warp per flagged row ----
__global__ void __launch_bounds__(256)
fixpair_kernel(const float* __restrict__ X, float* __restrict__ out) {
    int cnt = g_pair_count;
    int nw = gridDim.x * 8;
    int w = blockIdx.x * 8 + (threadIdx.x >> 5);
    int lane = threadIdx.x & 31;
    for (int e = w; e < cnt; e += nw) {
        int R = g_pair_rows[e];
        int2 cd = g_pair_cands[e];
        int v = R >> 13;
        const float* xrow = X + (size_t)R * ND;
        const float* Wv = g_Wt + (size_t)v * NK * ND;
        double s0 = wscore64(xrow, Wv + (size_t)cd.x * ND, lane);
        double s1 = wscore64(xrow, Wv + (size_t)cd.y * ND, lane);
        bool flip = (s1 < s0) || (s1 == s0 && cd.y < cd.x);
        if (flip) {
            const float4* wr = (const float4*)(Wv + (size_t)cd.y * ND);
            float4* orow = (float4*)(out + (size_t)R * ND);
            orow[lane] = wr[lane];
            orow[lane + 32] = wr[lane + 32];
            if (lane == 0) {
                g_idx[R] = cd.y;
                atomicAdd(&g_accum, s1 - s0);   // delta(sse) == delta(score)
            }
        }
    }
}

// ---- exact full-row rescore + correction for triple-flagged rows ----
__global__ void __launch_bounds__(256)
fix_kernel(const float* __restrict__ X, float* __restrict__ out) {
    __shared__ float xs[ND];
    __shared__ float wv[16];
    __shared__ int   wi[16];
    __shared__ int   s_kk, s_old;
    __shared__ double s_delta;
    int cnt = g_fix_count;
    for (int f = blockIdx.x; f < cnt; f += gridDim.x) {
        int R = g_fix_rows[f];
        int v = R >> 13;
        __syncthreads();
        xs[threadIdx.x] = X[(size_t)R * ND + threadIdx.x];
        __syncthreads();

        float b = FLT_MAX, s = FLT_MAX; int bi = 0x7FFFFFFF, si = 0x7FFFFFFF;
        #pragma unroll
        for (int kk = 0; kk < 4; ++kk) {
            int k = threadIdx.x * 4 + kk;
            const float* w = g_Wt + ((size_t)v * NK + k) * ND;
            float dot = 0.0f;
            #pragma unroll 8
            for (int d = 0; d < ND; ++d) dot = fmaf(xs[d], w[d], dot);
            float sc = g_wsq[v * NK + k] - 2.0f * dot;
            if (sc < b || (sc == b && k < bi)) { s = b; si = bi; b = sc; bi = k; }
            else if (sc < s || (sc == s && k < si)) { s = sc; si = k; }
        }
        const unsigned m = 0xFFFFFFFFu;
        #pragma unroll
        for (int off = 1; off < 32; off <<= 1) {
            float ob = __shfl_xor_sync(m, b, off);  int obi = __shfl_xor_sync(m, bi, off);
            float os = __shfl_xor_sync(m, s, off);  int osi = __shfl_xor_sync(m, si, off);
            bool tko = (ob < b) || (ob == b && obi < bi);
            float lb = tko ? b : ob; int lbi = tko ? bi : obi;
            float ws_ = tko ? os : s; int wsi = tko ? osi : si;
            if (tko) { b = ob; bi = obi; }
            if (ws_ < lb || (ws_ == lb && wsi < lbi)) { s = ws_; si = wsi; }
            else                                      { s = lb;  si = lbi; }
        }
        int wrp = threadIdx.x >> 5;
        if ((threadIdx.x & 31) == 0) { wv[wrp * 2] = b; wv[wrp * 2 + 1] = s; wi[wrp * 2] = bi; wi[wrp * 2 + 1] = si; }
        __syncthreads();
        if (threadIdx.x == 0) {
            float B = FLT_MAX, S = FLT_MAX; int Bi = 0x7FFFFFFF, Si = 0x7FFFFFFF;
            for (int q = 0; q < 16; ++q) {
                float vq = wv[q]; int iq = wi[q];
                if (vq < B || (vq == B && iq < Bi)) { S = B; Si = Bi; B = vq; Bi = iq; }
                else if (vq < S || (vq == S && iq < Si)) { S = vq; Si = iq; }
            }
            wv[0] = S - B; wi[0] = Bi; wi[1] = Si;
        }
        __syncthreads();
        if (threadIdx.x < 32) {
            int lane = threadIdx.x;
            int Bi = wi[0], Si = wi[1];
            const float* Wv = g_Wt + (size_t)v * NK * ND;
            int kk = Bi;
            if (wv[0] < MARGIN) {
                double sb2 = wscore64(xs, Wv + (size_t)Bi * ND, lane);
                double ss2 = wscore64(xs, Wv + (size_t)Si * ND, lane);
                if (ss2 < sb2 || (ss2 == sb2 && Si < Bi)) kk = Si;
            }
            int old = g_idx[R];
            double delta = 0.0;
            if (kk != old) {
                double sn = wscore64(xs, Wv + (size_t)kk * ND, lane);
                double so = wscore64(xs, Wv + (size_t)old * ND, lane);
                delta = sn - so;
            }
            if (lane == 0) { s_kk = kk; s_old = old; s_delta = delta; }
        }
        __syncthreads();
        if (s_kk != s_old) {
            out[(size_t)R * ND + threadIdx.x] = g_Wt[((size_t)v * NK + s_kk) * ND + threadIdx.x];
            if (threadIdx.x == 0) {
                g_idx[R] = s_kk;
                atomicAdd(&g_accum, s_delta);
            }
        }
        __syncthreads();
    }
}

// ---- loss writeback ----
__global__ void loss_kernel(float* __restrict__ out, long long out_size) {
    const long long VND = (long long)NV * NN * ND;
    double loss = 1.25 * g_accum / (double)VND;
    for (long long i = VND + threadIdx.x; i < out_size; i += blockDim.x)
        out[i] = (float)loss;
}

extern "C" void kernel_launch(void* const* d_in, const int* in_sizes, int n_in,
                              void* d_out, int out_size) {
    const float* X = (const float*)d_in[0];
    const float* E = (const float*)d_in[1];
    float* out = (float*)d_out;

    cudaFuncSetAttribute((const void*)gemm_argmin_kernel,
                         cudaFuncAttributeMaxDynamicSharedMemorySize, SMEM_TOTAL);

    transpose_kernel<<<dim3(NK / 32, ND / 32, NV), dim3(32, 8)>>>(E);
    wsq_kernel<<<2048, 256>>>();
    gemm_argmin_kernel<<<dim3(NN / 128, NV), 256, SMEM_TOTAL>>>(X, out);
    fixpair_kernel<<<256, 256>>>(X, out);
    fix_kernel<<<256, 256>>>(X, out);
    loss_kernel<<<1, 32>>>(out, (long long)out_size);
}